// round 1
// baseline (speedup 1.0000x reference)
#include <cuda_runtime.h>
#include <math.h>

#define NMAX 10000
#define EMAX 160000

// scratch (device globals: no runtime allocation)
__device__ float g_p0[NMAX * 16];
__device__ float g_p1[NMAX * 24];
__device__ float g_z[NMAX];
__device__ float g_hv[EMAX * 16];
__device__ float g_expv[EMAX];

// 16-wide dot: h in registers (literal-indexed), w = 4x float4 from smem (broadcast)
__device__ __forceinline__ float dot16(const float h[16], const float4* __restrict__ w) {
    float4 a = w[0], b = w[1], c = w[2], d = w[3];
    float s;
    s = h[0] * a.x;
    s = fmaf(h[1], a.y, s);  s = fmaf(h[2], a.z, s);  s = fmaf(h[3], a.w, s);
    s = fmaf(h[4], b.x, s);  s = fmaf(h[5], b.y, s);  s = fmaf(h[6], b.z, s);  s = fmaf(h[7], b.w, s);
    s = fmaf(h[8], c.x, s);  s = fmaf(h[9], c.y, s);  s = fmaf(h[10], c.z, s); s = fmaf(h[11], c.w, s);
    s = fmaf(h[12], d.x, s); s = fmaf(h[13], d.y, s); s = fmaf(h[14], d.z, s); s = fmaf(h[15], d.w, s);
    return s;
}

// -------- kernel 1: per-node p0/p1 = (x Wq) Wd with norms folded; zero z and out
__global__ void node_prep(const float* __restrict__ x,
                          const float* __restrict__ Wq0, const float* __restrict__ Wq1,
                          const float* __restrict__ Wd0, const float* __restrict__ Wd1,
                          float* __restrict__ out, int n) {
    __shared__ float C0[256];  // C0[u*16+v] = sum_w Wq0[u,w] Wd0[w,v] / 4
    __shared__ float C1[64];   // C1[u*8+v]  = sum_w Wq1[u,w] Wd1[w,v] / sqrt(24)
    int t = threadIdx.x;
    if (t < 256) {
        int u = t >> 4, v = t & 15;
        float s = 0.f;
        #pragma unroll
        for (int w = 0; w < 16; ++w) s = fmaf(Wq0[u * 16 + w], Wd0[w * 16 + v], s);
        C0[t] = s * 0.25f;
    }
    if (t < 64) {
        int u = t >> 3, v = t & 7;
        float s = 0.f;
        #pragma unroll
        for (int w = 0; w < 8; ++w) s = fmaf(Wq1[u * 8 + w], Wd1[w * 8 + v], s);
        C1[t] = s * 0.2041241452f;  // 1/(sqrt(8)*sqrt(3))
    }
    __syncthreads();
    int i = blockIdx.x * blockDim.x + t;
    if (i >= n) return;

    float x0[16];
    #pragma unroll
    for (int u = 0; u < 16; ++u) x0[u] = x[i * 40 + u];
    #pragma unroll
    for (int v = 0; v < 16; ++v) {
        float s = 0.f;
        #pragma unroll
        for (int u = 0; u < 16; ++u) s = fmaf(x0[u], C0[u * 16 + v], s);
        g_p0[i * 16 + v] = s;
    }
    float x1[24];
    #pragma unroll
    for (int k = 0; k < 24; ++k) x1[k] = x[i * 40 + 16 + k];
    #pragma unroll
    for (int v = 0; v < 8; ++v) {
        #pragma unroll
        for (int c = 0; c < 3; ++c) {
            float s = 0.f;
            #pragma unroll
            for (int u = 0; u < 8; ++u) s = fmaf(x1[u * 3 + c], C1[u * 8 + v], s);
            g_p1[i * 24 + v * 3 + c] = s;
        }
    }
    g_z[i] = 0.f;
    #pragma unroll
    for (int m = 0; m < 40; ++m) out[i * 40 + m] = 0.f;
}

// -------- kernel 2: per-edge score, expv, z accumulation; also caches h_v
__global__ __launch_bounds__(256) void edge_score(
    const float* __restrict__ x, const int* __restrict__ ei,
    const float* __restrict__ ea, const float* __restrict__ amf,
    const float* __restrict__ Wk1, const float* __restrict__ Wk2,
    const float* __restrict__ Wv1, int E) {
    __shared__ float Wc[9216];   // Wc[j*16+c] = Wk2[c, j]  (column-major by j)
    __shared__ float sK1[256], sV1[256];
    for (int idx = threadIdx.x; idx < 9216; idx += blockDim.x) {
        int j = idx >> 4, c = idx & 15;
        Wc[idx] = Wk2[c * 576 + j];
    }
    for (int idx = threadIdx.x; idx < 256; idx += blockDim.x) {
        sK1[idx] = Wk1[idx];
        sV1[idx] = Wv1[idx];
    }
    __syncthreads();
    const float4* W4 = reinterpret_cast<const float4*>(Wc);
    const float4* ea4 = reinterpret_cast<const float4*>(ea);

    for (int e = blockIdx.x * blockDim.x + threadIdx.x; e < E; e += gridDim.x * blockDim.x) {
        int src = ei[e], dst = ei[E + e];
        int xb = src * 40;
        float4 sh = ea4[e];
        float sh0 = sh.x, s1x = sh.y, s1y = sh.z, s1z = sh.w;
        float d = amf[e];

        // basis embedding: 1.14136*e^2*sqrt(16) * exp(-1/(diff+1) - 1/(1-diff)) where -1<diff<1
        float emb[16];
        #pragma unroll
        for (int b = 0; b < 16; ++b) {
            float cb = 8.0f * (float)(b + 1) / 17.0f;
            float diff = (d - cb) * 2.125f;  // /(8/17)
            float t1 = diff + 1.0f, t2 = 1.0f - diff;
            emb[b] = (t1 > 0.f && t2 > 0.f) ? 33.7342930f * __expf(-1.0f / t1 - 1.0f / t2) : 0.f;
        }
        float tc = 10.0f * (1.0f - d * 0.125f);
        float cut = (tc > 0.f) ? __expf(-1.0f / tc) : 0.f;

        // radial layer 1 (silu), both k and v paths; v cached to scratch
        float hk[16];
        #pragma unroll
        for (int c = 0; c < 16; ++c) {
            float sk = 0.f, sv = 0.f;
            #pragma unroll
            for (int b = 0; b < 16; ++b) {
                sk = fmaf(emb[b], sK1[b * 16 + c], sk);
                sv = fmaf(emb[b], sV1[b * 16 + c], sv);
            }
            sk *= 0.25f;
            sv *= 0.25f;
            hk[c] = sk / (1.f + __expf(-sk));
            g_hv[e * 16 + c] = sv / (1.f + __expf(-sv));
        }

        // per-edge query-side vectors (dst) and factors
        float p0[16], p1[24];
        #pragma unroll
        for (int v = 0; v < 16; ++v) p0[v] = g_p0[dst * 16 + v];
        #pragma unroll
        for (int k = 0; k < 24; ++k) p1[k] = g_p1[dst * 24 + k];
        float r[8];
        #pragma unroll
        for (int w = 0; w < 8; ++w)
            r[w] = p1[3 * w] * s1x + p1[3 * w + 1] * s1y + p1[3 * w + 2] * s1z;

        float score = 0.f, score3 = 0.f;
        // blocks B1 (w1: u16 x w16, j=u*16+w) and B2 (w2: u16 x w8, j=256+u*8+w)
        #pragma unroll 1
        for (int u = 0; u < 16; ++u) {
            float xu = __ldg(&x[xb + u]);
            const float4* wp = W4 + u * 64;
            float acc = 0.f;
            #pragma unroll
            for (int w = 0; w < 16; ++w) acc = fmaf(dot16(hk, wp + w * 4), p0[w], acc);
            const float4* wp2 = W4 + 1024 + u * 32;
            float acc2 = 0.f;
            #pragma unroll
            for (int w = 0; w < 8; ++w) acc2 = fmaf(dot16(hk, wp2 + w * 4), r[w], acc2);
            score = fmaf(xu * sh0, acc, score);
            score = fmaf(xu, acc2, score);
        }
        // blocks B3 (w3: u8 x w8, j=384+u*8+w) and B4 (w4: u8 x w16, j=448+u*16+w)
        #pragma unroll 1
        for (int u = 0; u < 8; ++u) {
            float ra = __ldg(&x[xb + 16 + 3 * u]);
            float rb = __ldg(&x[xb + 17 + 3 * u]);
            float rc = __ldg(&x[xb + 18 + 3 * u]);
            const float4* wp3 = W4 + 1536 + u * 32;
            float acc = 0.f;
            #pragma unroll
            for (int w = 0; w < 8; ++w) {
                float t3 = ra * p1[3 * w] + rb * p1[3 * w + 1] + rc * p1[3 * w + 2];
                acc = fmaf(dot16(hk, wp3 + w * 4), t3, acc);
            }
            score3 += acc;
            float d11 = (ra * s1x + rb * s1y + rc * s1z) * 0.57735027f;
            const float4* wp4 = W4 + 1792 + u * 64;
            float acc4 = 0.f;
            #pragma unroll
            for (int w = 0; w < 16; ++w) acc4 = fmaf(dot16(hk, wp4 + w * 4), p0[w], acc4);
            score = fmaf(d11, acc4, score);
        }
        score = fmaf(score3, sh0, score);
        score *= 0.0028527222f;  // 1/(4*sqrt(24)*sqrt(320))

        float ev = cut * __expf(score);
        g_expv[e] = ev;
        atomicAdd(&g_z[dst], ev);
    }
}

// -------- kernel 3: per-edge value tensor-product + weighted scatter to output
__global__ __launch_bounds__(256) void edge_value(
    const float* __restrict__ x, const int* __restrict__ ei,
    const float* __restrict__ ea, const float* __restrict__ Wv2,
    float* __restrict__ out, int E) {
    __shared__ float Wc[9216];
    for (int idx = threadIdx.x; idx < 9216; idx += blockDim.x) {
        int j = idx >> 4, c = idx & 15;
        Wc[idx] = Wv2[c * 576 + j];
    }
    __syncthreads();
    const float4* W4 = reinterpret_cast<const float4*>(Wc);
    const float4* ea4 = reinterpret_cast<const float4*>(ea);

    for (int e = blockIdx.x * blockDim.x + threadIdx.x; e < E; e += gridDim.x * blockDim.x) {
        int src = ei[e], dst = ei[E + e];
        int xb = src * 40;
        float4 sh = ea4[e];
        float sh0 = sh.x, s1x = sh.y, s1y = sh.z, s1z = sh.w;

        float hv[16];
        #pragma unroll
        for (int c = 0; c < 16; ++c) hv[c] = g_hv[e * 16 + c];

        float zz = g_z[dst];
        if (zz == 0.f) zz = 1.f;
        float al = g_expv[e] / zz;
        if (al < 0.f) al = 0.f;
        float f = sqrtf(al) * 0.0510310363f;  // we * 1/(4*sqrt(24))

        float v0[16], v1[24];
        #pragma unroll
        for (int w = 0; w < 16; ++w) v0[w] = 0.f;
        #pragma unroll
        for (int k = 0; k < 24; ++k) v1[k] = 0.f;

        // B1 + B2
        #pragma unroll 1
        for (int u = 0; u < 16; ++u) {
            float xu = __ldg(&x[xb + u]);
            float au = xu * sh0;
            const float4* wp = W4 + u * 64;
            #pragma unroll
            for (int w = 0; w < 16; ++w) v0[w] = fmaf(dot16(hv, wp + w * 4), au, v0[w]);
            const float4* wp2 = W4 + 1024 + u * 32;
            #pragma unroll
            for (int w = 0; w < 8; ++w) {
                float t = dot16(hv, wp2 + w * 4) * xu;
                v1[3 * w]     = fmaf(t, s1x, v1[3 * w]);
                v1[3 * w + 1] = fmaf(t, s1y, v1[3 * w + 1]);
                v1[3 * w + 2] = fmaf(t, s1z, v1[3 * w + 2]);
            }
        }
        // B3 + B4
        #pragma unroll 1
        for (int u = 0; u < 8; ++u) {
            float ra = __ldg(&x[xb + 16 + 3 * u]);
            float rb = __ldg(&x[xb + 17 + 3 * u]);
            float rc = __ldg(&x[xb + 18 + 3 * u]);
            float d11 = (ra * s1x + rb * s1y + rc * s1z) * 0.57735027f;
            float a = ra * sh0, b = rb * sh0, c = rc * sh0;
            const float4* wp3 = W4 + 1536 + u * 32;
            #pragma unroll
            for (int w = 0; w < 8; ++w) {
                float wv = dot16(hv, wp3 + w * 4);
                v1[3 * w]     = fmaf(wv, a, v1[3 * w]);
                v1[3 * w + 1] = fmaf(wv, b, v1[3 * w + 1]);
                v1[3 * w + 2] = fmaf(wv, c, v1[3 * w + 2]);
            }
            const float4* wp4 = W4 + 1792 + u * 64;
            #pragma unroll
            for (int w = 0; w < 16; ++w) v0[w] = fmaf(dot16(hv, wp4 + w * 4), d11, v0[w]);
        }

        float* ob = out + dst * 40;
        #pragma unroll
        for (int w = 0; w < 16; ++w) atomicAdd(ob + w, v0[w] * f);
        #pragma unroll
        for (int k = 0; k < 24; ++k) atomicAdd(ob + 16 + k, v1[k] * f);
    }
}

extern "C" void kernel_launch(void* const* d_in, const int* in_sizes, int n_in,
                              void* d_out, int out_size) {
    const float* x   = (const float*)d_in[0];
    const int*   ei  = (const int*)d_in[1];
    const float* ea  = (const float*)d_in[2];
    // d_in[3] = node_attr, d_in[4] = batch : unused by the reference math
    const float* amf = (const float*)d_in[5];
    const float* Wq0 = (const float*)d_in[6];
    const float* Wq1 = (const float*)d_in[7];
    const float* Wk1 = (const float*)d_in[8];
    const float* Wk2 = (const float*)d_in[9];
    const float* Wv1 = (const float*)d_in[10];
    const float* Wv2 = (const float*)d_in[11];
    const float* Wd0 = (const float*)d_in[12];
    const float* Wd1 = (const float*)d_in[13];
    float* out = (float*)d_out;

    int n = in_sizes[0] / 40;
    int E = in_sizes[2] / 4;

    node_prep<<<(n + 255) / 256, 256>>>(x, Wq0, Wq1, Wd0, Wd1, out, n);

    int grid = (E + 255) / 256;
    if (grid > 4096) grid = 4096;
    edge_score<<<grid, 256>>>(x, ei, ea, amf, Wk1, Wk2, Wv1, E);
    edge_value<<<grid, 256>>>(x, ei, ea, Wv2, out, E);
}

// round 2
// speedup vs baseline: 1.2120x; 1.2120x over previous
#include <cuda_runtime.h>
#include <math.h>

#define NMAX 10000
#define EMAX 160000

typedef unsigned long long ull;

// scratch (device globals: no runtime allocation)
__device__ float g_p0[NMAX * 16];
__device__ float g_p1[NMAX * 24];
__device__ float g_z[NMAX];
__device__ float4 g_hv[EMAX * 4];
__device__ float g_expv[EMAX];

// ---------- packed f32x2 primitives ----------
__device__ __forceinline__ ull pk2(float a) {
    ull r; asm("mov.b64 %0, {%1,%1};" : "=l"(r) : "f"(a)); return r;
}
__device__ __forceinline__ ull pk(float a, float b) {
    ull r; asm("mov.b64 %0, {%1,%2};" : "=l"(r) : "f"(a), "f"(b)); return r;
}
__device__ __forceinline__ float2 upk(ull a) {
    float2 f; asm("mov.b64 {%0,%1}, %2;" : "=f"(f.x), "=f"(f.y) : "l"(a)); return f;
}
__device__ __forceinline__ ull f2fma(ull a, ull b, ull c) {
    ull d; asm("fma.rn.f32x2 %0, %1, %2, %3;" : "=l"(d) : "l"(a), "l"(b), "l"(c)); return d;
}
__device__ __forceinline__ ull f2mul(ull a, ull b) {
    ull d; asm("mul.rn.f32x2 %0, %1, %2;" : "=l"(d) : "l"(a), "l"(b)); return d;
}
__device__ __forceinline__ ull f2add(ull a, ull b) {
    ull d; asm("add.rn.f32x2 %0, %1, %2;" : "=l"(d) : "l"(a), "l"(b)); return d;
}

// column = 16 floats = 4 ulonglong2. Accumulate f * col into T[8].
__device__ __forceinline__ void colmul8(ull T[8], const ulonglong2* __restrict__ c, ull f) {
    ulonglong2 c0 = c[0], c1 = c[1], c2 = c[2], c3 = c[3];
    T[0] = f2mul(f, c0.x); T[1] = f2mul(f, c0.y);
    T[2] = f2mul(f, c1.x); T[3] = f2mul(f, c1.y);
    T[4] = f2mul(f, c2.x); T[5] = f2mul(f, c2.y);
    T[6] = f2mul(f, c3.x); T[7] = f2mul(f, c3.y);
}
__device__ __forceinline__ void colfma8(ull T[8], const ulonglong2* __restrict__ c, ull f) {
    ulonglong2 c0 = c[0], c1 = c[1], c2 = c[2], c3 = c[3];
    T[0] = f2fma(f, c0.x, T[0]); T[1] = f2fma(f, c0.y, T[1]);
    T[2] = f2fma(f, c1.x, T[2]); T[3] = f2fma(f, c1.y, T[3]);
    T[4] = f2fma(f, c2.x, T[4]); T[5] = f2fma(f, c2.y, T[5]);
    T[6] = f2fma(f, c3.x, T[6]); T[7] = f2fma(f, c3.y, T[7]);
}
// packed dot of h[8] and T[8] -> still packed (caller hsums once)
__device__ __forceinline__ ull dot8p(const ull h[8], const ull T[8]) {
    ull s0 = f2mul(h[0], T[0]);
    ull s1 = f2mul(h[1], T[1]);
    s0 = f2fma(h[2], T[2], s0); s1 = f2fma(h[3], T[3], s1);
    s0 = f2fma(h[4], T[4], s0); s1 = f2fma(h[5], T[5], s1);
    s0 = f2fma(h[6], T[6], s0); s1 = f2fma(h[7], T[7], s1);
    return f2add(s0, s1);
}
// direct column dot with h (for W3 in value pass)
__device__ __forceinline__ float coldot(const ull h[8], const ulonglong2* __restrict__ c) {
    ulonglong2 c0 = c[0], c1 = c[1], c2 = c[2], c3 = c[3];
    ull s0 = f2mul(h[0], c0.x);
    ull s1 = f2mul(h[1], c0.y);
    s0 = f2fma(h[2], c1.x, s0); s1 = f2fma(h[3], c1.y, s1);
    s0 = f2fma(h[4], c2.x, s0); s1 = f2fma(h[5], c2.y, s1);
    s0 = f2fma(h[6], c3.x, s0); s1 = f2fma(h[7], c3.y, s1);
    float2 r = upk(f2add(s0, s1));
    return r.x + r.y;
}

// -------- kernel 1: per-node p0/p1 = (x Wq) Wd with norms folded; zero z and out
__global__ __launch_bounds__(128) void node_prep(
    const float* __restrict__ x,
    const float* __restrict__ Wq0, const float* __restrict__ Wq1,
    const float* __restrict__ Wd0, const float* __restrict__ Wd1,
    float* __restrict__ out, int n) {
    __shared__ float C0[256];
    __shared__ float C1[64];
    int t = threadIdx.x;
    for (int idx = t; idx < 256; idx += blockDim.x) {
        int u = idx >> 4, v = idx & 15;
        float s = 0.f;
        #pragma unroll
        for (int w = 0; w < 16; ++w) s = fmaf(Wq0[u * 16 + w], Wd0[w * 16 + v], s);
        C0[idx] = s * 0.25f;
    }
    if (t < 64) {
        int u = t >> 3, v = t & 7;
        float s = 0.f;
        #pragma unroll
        for (int w = 0; w < 8; ++w) s = fmaf(Wq1[u * 8 + w], Wd1[w * 8 + v], s);
        C1[t] = s * 0.2041241452f;  // 1/(sqrt(8)*sqrt(3))
    }
    __syncthreads();
    int i = blockIdx.x * blockDim.x + t;
    if (i >= n) return;

    float x0[16];
    #pragma unroll
    for (int u = 0; u < 16; ++u) x0[u] = x[i * 40 + u];
    #pragma unroll
    for (int v = 0; v < 16; ++v) {
        float s = 0.f;
        #pragma unroll
        for (int u = 0; u < 16; ++u) s = fmaf(x0[u], C0[u * 16 + v], s);
        g_p0[i * 16 + v] = s;
    }
    float x1[24];
    #pragma unroll
    for (int k = 0; k < 24; ++k) x1[k] = x[i * 40 + 16 + k];
    #pragma unroll
    for (int v = 0; v < 8; ++v) {
        #pragma unroll
        for (int c = 0; c < 3; ++c) {
            float s = 0.f;
            #pragma unroll
            for (int u = 0; u < 8; ++u) s = fmaf(x1[u * 3 + c], C1[u * 8 + v], s);
            g_p1[i * 24 + v * 3 + c] = s;
        }
    }
    g_z[i] = 0.f;
    float4 z4 = make_float4(0.f, 0.f, 0.f, 0.f);
    float4* o4 = reinterpret_cast<float4*>(out + i * 40);
    #pragma unroll
    for (int m = 0; m < 10; ++m) o4[m] = z4;
}

// -------- kernel 2: per-edge score, expv, z accumulation; also caches h_v
__global__ __launch_bounds__(128) void edge_score(
    const float* __restrict__ x, const int* __restrict__ ei,
    const float* __restrict__ ea, const float* __restrict__ amf,
    const float* __restrict__ Wk1, const float* __restrict__ Wk2,
    const float* __restrict__ Wv1, int E) {
    __shared__ __align__(16) float Wc[9216];   // Wc[j*16+c] = Wk2[c, j]
    __shared__ float sK1[256], sV1[256];
    for (int idx = threadIdx.x; idx < 9216; idx += blockDim.x) {
        int j = idx >> 4, c = idx & 15;
        Wc[idx] = Wk2[c * 576 + j];
    }
    for (int idx = threadIdx.x; idx < 256; idx += blockDim.x) {
        sK1[idx] = Wk1[idx];
        sV1[idx] = Wv1[idx];
    }
    __syncthreads();
    const ulonglong2* W2p = reinterpret_cast<const ulonglong2*>(Wc);
    const float4* ea4 = reinterpret_cast<const float4*>(ea);

    int e = blockIdx.x * blockDim.x + threadIdx.x;
    if (e >= E) return;

    int src = ei[e], dst = ei[E + e];
    int xb = src * 40;
    float4 sh = ea4[e];
    float sh0 = sh.x, s1x = sh.y, s1y = sh.z, s1z = sh.w;
    float d = amf[e];

    // basis embedding: exp(-1/t1 - 1/t2) = exp(-2/(1-diff^2)) since t1+t2=2
    float emb[16];
    #pragma unroll
    for (int b = 0; b < 16; ++b) {
        float cb = 8.0f * (float)(b + 1) / 17.0f;
        float diff = (d - cb) * 2.125f;
        float q = 1.0f - diff * diff;
        emb[b] = (q > 0.f) ? 33.7342930f * __expf(-2.0f * __frcp_rn(q)) : 0.f;
    }
    float tc = 10.0f * (1.0f - d * 0.125f);
    float cut = (tc > 0.f) ? __expf(-__frcp_rn(tc)) : 0.f;

    // radial layer 1 (silu): hk packed, hv cached to scratch
    ull hk2[8];
    float4* hvout = &g_hv[e * 4];
    #pragma unroll
    for (int cc = 0; cc < 8; ++cc) {
        float sk0 = 0.f, sk1 = 0.f, sv0 = 0.f, sv1 = 0.f;
        int c0 = 2 * cc;
        #pragma unroll
        for (int b = 0; b < 16; ++b) {
            float eb = emb[b];
            sk0 = fmaf(eb, sK1[b * 16 + c0], sk0);
            sk1 = fmaf(eb, sK1[b * 16 + c0 + 1], sk1);
            sv0 = fmaf(eb, sV1[b * 16 + c0], sv0);
            sv1 = fmaf(eb, sV1[b * 16 + c0 + 1], sv1);
        }
        sk0 *= 0.25f; sk1 *= 0.25f; sv0 *= 0.25f; sv1 *= 0.25f;
        float h0 = __fdividef(sk0, 1.f + __expf(-sk0));
        float h1 = __fdividef(sk1, 1.f + __expf(-sk1));
        hk2[cc] = pk(h0, h1);
        float v0s = __fdividef(sv0, 1.f + __expf(-sv0));
        float v1s = __fdividef(sv1, 1.f + __expf(-sv1));
        if (cc & 1) {
            float4 prev = hvout[cc >> 1];
            hvout[cc >> 1] = make_float4(prev.x, prev.y, v0s, v1s);
        } else {
            hvout[cc >> 1] = make_float4(v0s, v1s, 0.f, 0.f);
        }
    }

    // dst-side query vectors
    float p0[16], p1[24];
    #pragma unroll
    for (int v = 0; v < 16; ++v) p0[v] = g_p0[dst * 16 + v];
    #pragma unroll
    for (int k = 0; k < 24; ++k) p1[k] = g_p1[dst * 24 + k];
    float r[8];
    #pragma unroll
    for (int w = 0; w < 8; ++w)
        r[w] = p1[3 * w] * s1x + p1[3 * w + 1] * s1y + p1[3 * w + 2] * s1z;

    ull acc = pk2(0.f);
    ull acc3 = pk2(0.f);

    // B1 (j=u*16+w, factor p0[w], outer xu*sh0) + B2 (j=256+u*8+w, factor r[w], outer xu)
    #pragma unroll 1
    for (int u = 0; u < 16; ++u) {
        float xu = __ldg(&x[xb + u]);
        ull T[8], T2[8];
        colmul8(T, W2p + (u * 16) * 4, pk2(p0[0]));
        #pragma unroll
        for (int w = 1; w < 16; ++w) colfma8(T, W2p + (u * 16 + w) * 4, pk2(p0[w]));
        colmul8(T2, W2p + (256 + u * 8) * 4, pk2(r[0]));
        #pragma unroll
        for (int w = 1; w < 8; ++w) colfma8(T2, W2p + (256 + u * 8 + w) * 4, pk2(r[w]));
        acc = f2fma(pk2(xu * sh0), dot8p(hk2, T), acc);
        acc = f2fma(pk2(xu), dot8p(hk2, T2), acc);
    }
    // B3 (j=384+u*8+w, factor t3[u,w], sum scaled by sh0) + B4 (j=448+u*16+w, factor p0[w], outer d11[u])
    #pragma unroll 1
    for (int u = 0; u < 8; ++u) {
        float ra = __ldg(&x[xb + 16 + 3 * u]);
        float rb = __ldg(&x[xb + 17 + 3 * u]);
        float rc = __ldg(&x[xb + 18 + 3 * u]);
        ull T3[8], T4[8];
        {
            float t3 = ra * p1[0] + rb * p1[1] + rc * p1[2];
            colmul8(T3, W2p + (384 + u * 8) * 4, pk2(t3));
        }
        #pragma unroll
        for (int w = 1; w < 8; ++w) {
            float t3 = ra * p1[3 * w] + rb * p1[3 * w + 1] + rc * p1[3 * w + 2];
            colfma8(T3, W2p + (384 + u * 8 + w) * 4, pk2(t3));
        }
        colmul8(T4, W2p + (448 + u * 16) * 4, pk2(p0[0]));
        #pragma unroll
        for (int w = 1; w < 16; ++w) colfma8(T4, W2p + (448 + u * 16 + w) * 4, pk2(p0[w]));
        float d11 = (ra * s1x + rb * s1y + rc * s1z) * 0.57735027f;
        acc3 = f2add(acc3, dot8p(hk2, T3));
        acc = f2fma(pk2(d11), dot8p(hk2, T4), acc);
    }
    float2 a2 = upk(acc), b2 = upk(acc3);
    float score = (a2.x + a2.y + (b2.x + b2.y) * sh0) * 0.0028527222f;

    float ev = cut * __expf(score);
    g_expv[e] = ev;
    atomicAdd(&g_z[dst], ev);
}

// -------- kernel 3: per-edge value tensor-product + weighted scatter
__global__ __launch_bounds__(128) void edge_value(
    const float* __restrict__ x, const int* __restrict__ ei,
    const float* __restrict__ ea, const float* __restrict__ Wv2,
    float* __restrict__ out, int E) {
    __shared__ __align__(16) float Wc[9216];
    for (int idx = threadIdx.x; idx < 9216; idx += blockDim.x) {
        int j = idx >> 4, c = idx & 15;
        Wc[idx] = Wv2[c * 576 + j];
    }
    __syncthreads();
    const ulonglong2* W2p = reinterpret_cast<const ulonglong2*>(Wc);
    const float4* ea4 = reinterpret_cast<const float4*>(ea);

    int e = blockIdx.x * blockDim.x + threadIdx.x;
    if (e >= E) return;

    int src = ei[e], dst = ei[E + e];
    int xb = src * 40;
    float4 sh = ea4[e];
    float sh0 = sh.x, s1x = sh.y, s1y = sh.z, s1z = sh.w;

    ull hv2[8];
    {
        const float4* hvp = &g_hv[e * 4];
        #pragma unroll
        for (int k = 0; k < 4; ++k) {
            float4 q = hvp[k];
            hv2[2 * k]     = pk(q.x, q.y);
            hv2[2 * k + 1] = pk(q.z, q.w);
        }
    }

    float zz = g_z[dst];
    if (zz == 0.f) zz = 1.f;
    float al = g_expv[e] / zz;
    if (al < 0.f) al = 0.f;
    float fs = sqrtf(al) * 0.0510310363f;  // sqrt(alpha)/(4*sqrt(24))

    // src features
    float x0r[16], a0[16];
    #pragma unroll
    for (int u = 0; u < 16; ++u) { x0r[u] = __ldg(&x[xb + u]); a0[u] = x0r[u] * sh0; }
    float x1s[24], dd[8];
    #pragma unroll
    for (int u = 0; u < 8; ++u) {
        float ra = __ldg(&x[xb + 16 + 3 * u]);
        float rb = __ldg(&x[xb + 17 + 3 * u]);
        float rc = __ldg(&x[xb + 18 + 3 * u]);
        dd[u] = (ra * s1x + rb * s1y + rc * s1z) * 0.57735027f;
        x1s[3 * u] = ra * sh0; x1s[3 * u + 1] = rb * sh0; x1s[3 * u + 2] = rc * sh0;
    }

    float* ob = out + dst * 40;

    // o0[w] = hv . ( sum_u a0[u] W1col(u,w) + sum_u dd[u] W4col(u,w) )
    #pragma unroll 1
    for (int w = 0; w < 16; ++w) {
        ull U[8];
        colmul8(U, W2p + (w) * 4, pk2(a0[0]));
        #pragma unroll
        for (int u = 1; u < 16; ++u) colfma8(U, W2p + (u * 16 + w) * 4, pk2(a0[u]));
        #pragma unroll
        for (int u = 0; u < 8; ++u) colfma8(U, W2p + (448 + u * 16 + w) * 4, pk2(dd[u]));
        float2 s2 = upk(dot8p(hv2, U));
        atomicAdd(ob + w, (s2.x + s2.y) * fs);
    }

    // o1[w,:] = (hv . sum_u x0[u] W2col(u,w)) * sh1  +  sum_u (hv . W3col(u,w)) * x1s[u,:]
    #pragma unroll 1
    for (int w = 0; w < 8; ++w) {
        ull U[8];
        colmul8(U, W2p + (256 + w) * 4, pk2(x0r[0]));
        #pragma unroll
        for (int u = 1; u < 16; ++u) colfma8(U, W2p + (256 + u * 8 + w) * 4, pk2(x0r[u]));
        float2 t2 = upk(dot8p(hv2, U));
        float Aw = t2.x + t2.y;
        float vx = Aw * s1x, vy = Aw * s1y, vz = Aw * s1z;
        #pragma unroll
        for (int u = 0; u < 8; ++u) {
            float s = coldot(hv2, W2p + (384 + u * 8 + w) * 4);
            vx = fmaf(s, x1s[3 * u], vx);
            vy = fmaf(s, x1s[3 * u + 1], vy);
            vz = fmaf(s, x1s[3 * u + 2], vz);
        }
        atomicAdd(ob + 16 + 3 * w, vx * fs);
        atomicAdd(ob + 17 + 3 * w, vy * fs);
        atomicAdd(ob + 18 + 3 * w, vz * fs);
    }
}

extern "C" void kernel_launch(void* const* d_in, const int* in_sizes, int n_in,
                              void* d_out, int out_size) {
    const float* x   = (const float*)d_in[0];
    const int*   ei  = (const int*)d_in[1];
    const float* ea  = (const float*)d_in[2];
    const float* amf = (const float*)d_in[5];
    const float* Wq0 = (const float*)d_in[6];
    const float* Wq1 = (const float*)d_in[7];
    const float* Wk1 = (const float*)d_in[8];
    const float* Wk2 = (const float*)d_in[9];
    const float* Wv1 = (const float*)d_in[10];
    const float* Wv2 = (const float*)d_in[11];
    const float* Wd0 = (const float*)d_in[12];
    const float* Wd1 = (const float*)d_in[13];
    float* out = (float*)d_out;

    int n = in_sizes[0] / 40;
    int E = in_sizes[2] / 4;

    node_prep<<<(n + 127) / 128, 128>>>(x, Wq0, Wq1, Wd0, Wd1, out, n);

    int grid = (E + 127) / 128;
    edge_score<<<grid, 128>>>(x, ei, ea, amf, Wk1, Wk2, Wv1, E);
    edge_value<<<grid, 128>>>(x, ei, ea, Wv2, out, E);
}

// round 3
// speedup vs baseline: 1.3310x; 1.0981x over previous
#include <cuda_runtime.h>
#include <math.h>

#define NMAX 10000
#define EMAX 160000
typedef unsigned long long ull;

// device scratch (no runtime allocation)
__device__ float g_p0[NMAX * 16];
__device__ float g_p1[NMAX * 24];
__device__ float g_z[NMAX];
__device__ float g_WkT[9216];   // [j*16+c] transposed Wk2
__device__ float g_WvT[9216];

// ---------- packed f32x2 primitives ----------
__device__ __forceinline__ ull pk2(float a) {
    ull r; asm("mov.b64 %0, {%1,%1};" : "=l"(r) : "f"(a)); return r;
}
__device__ __forceinline__ ull pk(float a, float b) {
    ull r; asm("mov.b64 %0, {%1,%2};" : "=l"(r) : "f"(a), "f"(b)); return r;
}
__device__ __forceinline__ float2 upk(ull a) {
    float2 f; asm("mov.b64 {%0,%1}, %2;" : "=f"(f.x), "=f"(f.y) : "l"(a)); return f;
}
__device__ __forceinline__ ull f2fma(ull a, ull b, ull c) {
    ull d; asm("fma.rn.f32x2 %0, %1, %2, %3;" : "=l"(d) : "l"(a), "l"(b), "l"(c)); return d;
}
__device__ __forceinline__ ull f2mul(ull a, ull b) {
    ull d; asm("mul.rn.f32x2 %0, %1, %2;" : "=l"(d) : "l"(a), "l"(b)); return d;
}
__device__ __forceinline__ ull f2add(ull a, ull b) {
    ull d; asm("add.rn.f32x2 %0, %1, %2;" : "=l"(d) : "l"(a), "l"(b)); return d;
}
__device__ __forceinline__ void colmul8(ull T[8], const ulonglong2* __restrict__ c, ull f) {
    ulonglong2 c0 = c[0], c1 = c[1], c2 = c[2], c3 = c[3];
    T[0] = f2mul(f, c0.x); T[1] = f2mul(f, c0.y);
    T[2] = f2mul(f, c1.x); T[3] = f2mul(f, c1.y);
    T[4] = f2mul(f, c2.x); T[5] = f2mul(f, c2.y);
    T[6] = f2mul(f, c3.x); T[7] = f2mul(f, c3.y);
}
__device__ __forceinline__ void colfma8(ull T[8], const ulonglong2* __restrict__ c, ull f) {
    ulonglong2 c0 = c[0], c1 = c[1], c2 = c[2], c3 = c[3];
    T[0] = f2fma(f, c0.x, T[0]); T[1] = f2fma(f, c0.y, T[1]);
    T[2] = f2fma(f, c1.x, T[2]); T[3] = f2fma(f, c1.y, T[3]);
    T[4] = f2fma(f, c2.x, T[4]); T[5] = f2fma(f, c2.y, T[5]);
    T[6] = f2fma(f, c3.x, T[6]); T[7] = f2fma(f, c3.y, T[7]);
}
__device__ __forceinline__ ull dot8p(const ull h[8], const ull T[8]) {
    ull s0 = f2mul(h[0], T[0]);
    ull s1 = f2mul(h[1], T[1]);
    s0 = f2fma(h[2], T[2], s0); s1 = f2fma(h[3], T[3], s1);
    s0 = f2fma(h[4], T[4], s0); s1 = f2fma(h[5], T[5], s1);
    s0 = f2fma(h[6], T[6], s0); s1 = f2fma(h[7], T[7], s1);
    return f2add(s0, s1);
}
__device__ __forceinline__ float coldot(const ull h[8], const ulonglong2* __restrict__ c) {
    ulonglong2 c0 = c[0], c1 = c[1], c2 = c[2], c3 = c[3];
    ull s0 = f2mul(h[0], c0.x);
    ull s1 = f2mul(h[1], c0.y);
    s0 = f2fma(h[2], c1.x, s0); s1 = f2fma(h[3], c1.y, s1);
    s0 = f2fma(h[4], c2.x, s0); s1 = f2fma(h[5], c2.y, s1);
    s0 = f2fma(h[6], c3.x, s0); s1 = f2fma(h[7], c3.y, s1);
    float2 r = upk(f2add(s0, s1));
    return r.x + r.y;
}

// -------- one-time weight transpose (coalesced writes)
__global__ void transpose_w(const float* __restrict__ Wk2, const float* __restrict__ Wv2) {
    int idx = blockIdx.x * 256 + threadIdx.x;
    if (idx < 9216) {
        g_WkT[idx] = Wk2[(idx & 15) * 576 + (idx >> 4)];
    } else if (idx < 18432) {
        int t = idx - 9216;
        g_WvT[t] = Wv2[(t & 15) * 576 + (t >> 4)];
    }
}

// -------- per-node p0/p1 = x(WqWd) with norms folded; zero z and out
__global__ __launch_bounds__(128) void node_prep(
    const float* __restrict__ x,
    const float* __restrict__ Wq0, const float* __restrict__ Wq1,
    const float* __restrict__ Wd0, const float* __restrict__ Wd1,
    float* __restrict__ out, int n) {
    __shared__ float C0[256];
    __shared__ float C1[64];
    int t = threadIdx.x;
    for (int idx = t; idx < 256; idx += blockDim.x) {
        int u = idx >> 4, v = idx & 15;
        float s = 0.f;
        #pragma unroll
        for (int w = 0; w < 16; ++w) s = fmaf(Wq0[u * 16 + w], Wd0[w * 16 + v], s);
        C0[idx] = s * 0.25f;
    }
    if (t < 64) {
        int u = t >> 3, v = t & 7;
        float s = 0.f;
        #pragma unroll
        for (int w = 0; w < 8; ++w) s = fmaf(Wq1[u * 8 + w], Wd1[w * 8 + v], s);
        C1[t] = s * 0.2041241452f;  // 1/(sqrt(8)*sqrt(3))
    }
    __syncthreads();
    int i = blockIdx.x * blockDim.x + t;
    if (i >= n) return;

    float x0[16];
    #pragma unroll
    for (int u = 0; u < 16; ++u) x0[u] = x[i * 40 + u];
    #pragma unroll
    for (int v = 0; v < 16; ++v) {
        float s = 0.f;
        #pragma unroll
        for (int u = 0; u < 16; ++u) s = fmaf(x0[u], C0[u * 16 + v], s);
        g_p0[i * 16 + v] = s;
    }
    float x1[24];
    #pragma unroll
    for (int k = 0; k < 24; ++k) x1[k] = x[i * 40 + 16 + k];
    #pragma unroll
    for (int v = 0; v < 8; ++v) {
        #pragma unroll
        for (int c = 0; c < 3; ++c) {
            float s = 0.f;
            #pragma unroll
            for (int u = 0; u < 8; ++u) s = fmaf(x1[u * 3 + c], C1[u * 8 + v], s);
            g_p1[i * 24 + v * 3 + c] = s;
        }
    }
    g_z[i] = 0.f;
    float4 z4 = make_float4(0.f, 0.f, 0.f, 0.f);
    float4* o4 = reinterpret_cast<float4*>(out + i * 40);
    #pragma unroll
    for (int m = 0; m < 10; ++m) o4[m] = z4;
}

// -------- fused edge kernel: score + unnormalized value scatter
__global__ __launch_bounds__(128) void edge_fused(
    const float* __restrict__ x, const int* __restrict__ ei,
    const float* __restrict__ ea, const float* __restrict__ amf,
    const float* __restrict__ Wk1, const float* __restrict__ Wv1,
    float* __restrict__ out, int E) {
    extern __shared__ float sm[];
    float* Wk = sm;             // 9216 floats, [j*16+c]
    float* Wv = sm + 9216;      // 9216
    float* K1 = sm + 18432;     // 256
    float* V1 = sm + 18688;     // 256  (total 18944 floats = 75776 B)
    {
        float4* s4 = reinterpret_cast<float4*>(sm);
        const float4* k4 = reinterpret_cast<const float4*>(g_WkT);
        const float4* v4 = reinterpret_cast<const float4*>(g_WvT);
        for (int i = threadIdx.x; i < 2304; i += 128) s4[i] = k4[i];
        for (int i = threadIdx.x; i < 2304; i += 128) s4[2304 + i] = v4[i];
        if (threadIdx.x < 64)
            reinterpret_cast<float4*>(K1)[threadIdx.x] =
                reinterpret_cast<const float4*>(Wk1)[threadIdx.x];
        else if (threadIdx.x < 128)
            reinterpret_cast<float4*>(V1)[threadIdx.x - 64] =
                reinterpret_cast<const float4*>(Wv1)[threadIdx.x - 64];
    }
    __syncthreads();

    int e = blockIdx.x * 128 + threadIdx.x;
    if (e >= E) return;

    int src = ei[e], dst = ei[E + e];
    const float4 sh = reinterpret_cast<const float4*>(ea)[e];
    const float sh0 = sh.x, s1x = sh.y, s1y = sh.z, s1z = sh.w;
    const float d = amf[e];

    float tc = 10.0f * (1.0f - d * 0.125f);
    float cut = (tc > 0.f) ? __expf(-__frcp_rn(tc)) : 0.f;

    // ---- emb + hk (hv recomputed later to keep walk registers lean)
    float emb[16];
    #pragma unroll
    for (int b = 0; b < 16; ++b) {
        float cb = 0.47058824f * (float)(b + 1);
        float diff = (d - cb) * 2.125f;
        float q = 1.0f - diff * diff;
        emb[b] = (q > 0.f) ? 33.7342930f * __expf(-2.0f * __frcp_rn(q)) : 0.f;
    }
    ull hk2[8];
    #pragma unroll
    for (int cc = 0; cc < 8; ++cc) {
        float s0 = 0.f, s1 = 0.f; int c0 = 2 * cc;
        #pragma unroll
        for (int b = 0; b < 16; ++b) {
            float eb = emb[b];
            s0 = fmaf(eb, K1[b * 16 + c0], s0);
            s1 = fmaf(eb, K1[b * 16 + c0 + 1], s1);
        }
        s0 *= 0.25f; s1 *= 0.25f;
        hk2[cc] = pk(__fdividef(s0, 1.f + __expf(-s0)),
                     __fdividef(s1, 1.f + __expf(-s1)));
    }

    // ---- gather src features, dst query vectors
    const float4* xp4 = reinterpret_cast<const float4*>(x + src * 40);
    float x0r[16];
    {
        float4 t0 = xp4[0], t1 = xp4[1], t2 = xp4[2], t3 = xp4[3];
        x0r[0] = t0.x; x0r[1] = t0.y; x0r[2] = t0.z; x0r[3] = t0.w;
        x0r[4] = t1.x; x0r[5] = t1.y; x0r[6] = t1.z; x0r[7] = t1.w;
        x0r[8] = t2.x; x0r[9] = t2.y; x0r[10] = t2.z; x0r[11] = t2.w;
        x0r[12] = t3.x; x0r[13] = t3.y; x0r[14] = t3.z; x0r[15] = t3.w;
    }
    float xs1s[24], dd[8];
    {
        float x1r[24];
        #pragma unroll
        for (int k = 0; k < 6; ++k) {
            float4 t = xp4[4 + k];
            x1r[4 * k] = t.x; x1r[4 * k + 1] = t.y; x1r[4 * k + 2] = t.z; x1r[4 * k + 3] = t.w;
        }
        #pragma unroll
        for (int u = 0; u < 8; ++u) {
            float ra = x1r[3 * u], rb = x1r[3 * u + 1], rc = x1r[3 * u + 2];
            dd[u] = (ra * s1x + rb * s1y + rc * s1z) * 0.57735027f;
            xs1s[3 * u] = ra * sh0; xs1s[3 * u + 1] = rb * sh0; xs1s[3 * u + 2] = rc * sh0;
        }
    }
    float p0[16];
    {
        const float4* pp = reinterpret_cast<const float4*>(g_p0 + dst * 16);
        float4 t0 = pp[0], t1 = pp[1], t2 = pp[2], t3 = pp[3];
        p0[0] = t0.x; p0[1] = t0.y; p0[2] = t0.z; p0[3] = t0.w;
        p0[4] = t1.x; p0[5] = t1.y; p0[6] = t1.z; p0[7] = t1.w;
        p0[8] = t2.x; p0[9] = t2.y; p0[10] = t2.z; p0[11] = t2.w;
        p0[12] = t3.x; p0[13] = t3.y; p0[14] = t3.z; p0[15] = t3.w;
    }

    // ---- score walk: m[c] += g_j * Wk[:,j]
    const ulonglong2* WK = reinterpret_cast<const ulonglong2*>(Wk);
    ull m[8];
    {   // block1: j=u*16+w, g = (x0[u]*sh0) * p0[w]
        float au = x0r[0] * sh0;
        colmul8(m, WK, pk2(au * p0[0]));
        #pragma unroll
        for (int w = 1; w < 16; ++w) colfma8(m, WK + w * 4, pk2(au * p0[w]));
    }
    #pragma unroll 1
    for (int u = 1; u < 16; ++u) {
        float au = x0r[u] * sh0;
        #pragma unroll
        for (int w = 0; w < 16; ++w) colfma8(m, WK + (u * 16 + w) * 4, pk2(au * p0[w]));
    }
    // block4: j=448+u*16+w, g = dd[u]*p0[w]
    #pragma unroll 1
    for (int u = 0; u < 8; ++u) {
        float du = dd[u];
        #pragma unroll
        for (int w = 0; w < 16; ++w) colfma8(m, WK + (448 + u * 16 + w) * 4, pk2(du * p0[w]));
    }
    // dst p1 + r (loaded late to cap live registers)
    float p1[24];
    {
        const float4* pp = reinterpret_cast<const float4*>(g_p1 + dst * 24);
        #pragma unroll
        for (int k = 0; k < 6; ++k) {
            float4 t = pp[k];
            p1[4 * k] = t.x; p1[4 * k + 1] = t.y; p1[4 * k + 2] = t.z; p1[4 * k + 3] = t.w;
        }
    }
    float r[8];
    #pragma unroll
    for (int w = 0; w < 8; ++w)
        r[w] = p1[3 * w] * s1x + p1[3 * w + 1] * s1y + p1[3 * w + 2] * s1z;
    // block2: j=256+u*8+w, g = x0[u]*r[w]
    #pragma unroll 1
    for (int u = 0; u < 16; ++u) {
        float xu = x0r[u];
        #pragma unroll
        for (int w = 0; w < 8; ++w) colfma8(m, WK + (256 + u * 8 + w) * 4, pk2(xu * r[w]));
    }
    // block3: j=384+u*8+w, g = xs1s[u,:].p1[w,:]
    #pragma unroll 1
    for (int u = 0; u < 8; ++u) {
        float a = xs1s[3 * u], b = xs1s[3 * u + 1], c = xs1s[3 * u + 2];
        #pragma unroll
        for (int w = 0; w < 8; ++w) {
            float g = a * p1[3 * w] + b * p1[3 * w + 1] + c * p1[3 * w + 2];
            colfma8(m, WK + (384 + u * 8 + w) * 4, pk2(g));
        }
    }
    float2 sc2 = upk(dot8p(hk2, m));
    float score = (sc2.x + sc2.y) * 0.0028527222f;  // 1/(4*sqrt(24)*sqrt(320))
    float ev = cut * __expf(score);
    atomicAdd(&g_z[dst], ev);
    float fs = sqrtf(ev) * 0.0510310363f;           // sqrt(ev)/(4*sqrt(24))

    // ---- rebuild emb, compute hv
    #pragma unroll
    for (int b = 0; b < 16; ++b) {
        float cb = 0.47058824f * (float)(b + 1);
        float diff = (d - cb) * 2.125f;
        float q = 1.0f - diff * diff;
        emb[b] = (q > 0.f) ? 33.7342930f * __expf(-2.0f * __frcp_rn(q)) : 0.f;
    }
    ull hv2[8];
    #pragma unroll
    for (int cc = 0; cc < 8; ++cc) {
        float s0 = 0.f, s1 = 0.f; int c0 = 2 * cc;
        #pragma unroll
        for (int b = 0; b < 16; ++b) {
            float eb = emb[b];
            s0 = fmaf(eb, V1[b * 16 + c0], s0);
            s1 = fmaf(eb, V1[b * 16 + c0 + 1], s1);
        }
        s0 *= 0.25f; s1 *= 0.25f;
        hv2[cc] = pk(__fdividef(s0, 1.f + __expf(-s0)),
                     __fdividef(s1, 1.f + __expf(-s1)));
    }

    // ---- value walk + scatter
    const ulonglong2* WV = reinterpret_cast<const ulonglong2*>(Wv);
    float a0[16];
    #pragma unroll
    for (int u = 0; u < 16; ++u) a0[u] = x0r[u] * sh0;
    float* ob = out + dst * 40;

    // o0[w] = hv . ( sum_u a0[u] W1col + sum_u dd[u] W4col )
    #pragma unroll 1
    for (int w = 0; w < 16; ++w) {
        ull U[8];
        colmul8(U, WV + w * 4, pk2(a0[0]));
        #pragma unroll
        for (int u = 1; u < 16; ++u) colfma8(U, WV + (u * 16 + w) * 4, pk2(a0[u]));
        #pragma unroll
        for (int u = 0; u < 8; ++u) colfma8(U, WV + (448 + u * 16 + w) * 4, pk2(dd[u]));
        float2 s2 = upk(dot8p(hv2, U));
        atomicAdd(ob + w, (s2.x + s2.y) * fs);
    }
    // o1[w,:] = (hv . sum_u x0[u] W2col) * sh1 + sum_u (hv . W3col) * xs1s[u,:]
    #pragma unroll 1
    for (int w = 0; w < 8; ++w) {
        ull U[8];
        colmul8(U, WV + (256 + w) * 4, pk2(x0r[0]));
        #pragma unroll
        for (int u = 1; u < 16; ++u) colfma8(U, WV + (256 + u * 8 + w) * 4, pk2(x0r[u]));
        float2 t2 = upk(dot8p(hv2, U));
        float Aw = t2.x + t2.y;
        float vx = Aw * s1x, vy = Aw * s1y, vz = Aw * s1z;
        #pragma unroll
        for (int u = 0; u < 8; ++u) {
            float s = coldot(hv2, WV + (384 + u * 8 + w) * 4);
            vx = fmaf(s, xs1s[3 * u], vx);
            vy = fmaf(s, xs1s[3 * u + 1], vy);
            vz = fmaf(s, xs1s[3 * u + 2], vz);
        }
        atomicAdd(ob + 16 + 3 * w, vx * fs);
        atomicAdd(ob + 17 + 3 * w, vy * fs);
        atomicAdd(ob + 18 + 3 * w, vz * fs);
    }
}

// -------- epilogue: out[i] *= rsqrt(z[i])
__global__ void normalize(float* __restrict__ out, int n) {
    int i = blockIdx.x * 128 + threadIdx.x;
    if (i >= n) return;
    float zz = g_z[i];
    if (zz <= 0.f) zz = 1.f;
    float s = rsqrtf(zz);
    float4* o4 = reinterpret_cast<float4*>(out + i * 40);
    #pragma unroll
    for (int m = 0; m < 10; ++m) {
        float4 v = o4[m];
        v.x *= s; v.y *= s; v.z *= s; v.w *= s;
        o4[m] = v;
    }
}

extern "C" void kernel_launch(void* const* d_in, const int* in_sizes, int n_in,
                              void* d_out, int out_size) {
    const float* x   = (const float*)d_in[0];
    const int*   ei  = (const int*)d_in[1];
    const float* ea  = (const float*)d_in[2];
    const float* amf = (const float*)d_in[5];
    const float* Wq0 = (const float*)d_in[6];
    const float* Wq1 = (const float*)d_in[7];
    const float* Wk1 = (const float*)d_in[8];
    const float* Wk2 = (const float*)d_in[9];
    const float* Wv1 = (const float*)d_in[10];
    const float* Wv2 = (const float*)d_in[11];
    const float* Wd0 = (const float*)d_in[12];
    const float* Wd1 = (const float*)d_in[13];
    float* out = (float*)d_out;

    int n = in_sizes[0] / 40;
    int E = in_sizes[2] / 4;

    cudaFuncSetAttribute(edge_fused, cudaFuncAttributeMaxDynamicSharedMemorySize, 75776);

    transpose_w<<<72, 256>>>(Wk2, Wv2);
    node_prep<<<(n + 127) / 128, 128>>>(x, Wq0, Wq1, Wd0, Wd1, out, n);
    edge_fused<<<(E + 127) / 128, 128, 75776>>>(x, ei, ea, amf, Wk1, Wv1, out, E);
    normalize<<<(n + 127) / 128, 128>>>(out, n);
}

// round 4
// speedup vs baseline: 1.3415x; 1.0079x over previous
#include <cuda_runtime.h>
#include <math.h>

#define NMAX 10000
#define EMAX 160000
#define TBL 16384
typedef unsigned long long ull;

// device scratch (no runtime allocation)
__device__ float g_p0[NMAX * 16];
__device__ float g_p1[NMAX * 24];
__device__ float g_z[NMAX];
__device__ float g_expv[EMAX];
__device__ float g_WkT[9216];      // [j*16+c]
__device__ float g_WvT[9216];
__device__ float g_tk[TBL * 16];   // hk(d) table
__device__ float g_tv[TBL * 16];   // hv(d) table

// ---------- packed f32x2 primitives ----------
__device__ __forceinline__ ull pk2(float a) {
    ull r; asm("mov.b64 %0, {%1,%1};" : "=l"(r) : "f"(a)); return r;
}
__device__ __forceinline__ ull pk(float a, float b) {
    ull r; asm("mov.b64 %0, {%1,%2};" : "=l"(r) : "f"(a), "f"(b)); return r;
}
__device__ __forceinline__ float2 upk(ull a) {
    float2 f; asm("mov.b64 {%0,%1}, %2;" : "=f"(f.x), "=f"(f.y) : "l"(a)); return f;
}
__device__ __forceinline__ ull f2fma(ull a, ull b, ull c) {
    ull d; asm("fma.rn.f32x2 %0, %1, %2, %3;" : "=l"(d) : "l"(a), "l"(b), "l"(c)); return d;
}
__device__ __forceinline__ ull f2mul(ull a, ull b) {
    ull d; asm("mul.rn.f32x2 %0, %1, %2;" : "=l"(d) : "l"(a), "l"(b)); return d;
}
__device__ __forceinline__ ull f2add(ull a, ull b) {
    ull d; asm("add.rn.f32x2 %0, %1, %2;" : "=l"(d) : "l"(a), "l"(b)); return d;
}
__device__ __forceinline__ void colmul8(ull T[8], const ulonglong2* __restrict__ c, ull f) {
    ulonglong2 c0 = c[0], c1 = c[1], c2 = c[2], c3 = c[3];
    T[0] = f2mul(f, c0.x); T[1] = f2mul(f, c0.y);
    T[2] = f2mul(f, c1.x); T[3] = f2mul(f, c1.y);
    T[4] = f2mul(f, c2.x); T[5] = f2mul(f, c2.y);
    T[6] = f2mul(f, c3.x); T[7] = f2mul(f, c3.y);
}
__device__ __forceinline__ void colfma8(ull T[8], const ulonglong2* __restrict__ c, ull f) {
    ulonglong2 c0 = c[0], c1 = c[1], c2 = c[2], c3 = c[3];
    T[0] = f2fma(f, c0.x, T[0]); T[1] = f2fma(f, c0.y, T[1]);
    T[2] = f2fma(f, c1.x, T[2]); T[3] = f2fma(f, c1.y, T[3]);
    T[4] = f2fma(f, c2.x, T[4]); T[5] = f2fma(f, c2.y, T[5]);
    T[6] = f2fma(f, c3.x, T[6]); T[7] = f2fma(f, c3.y, T[7]);
}
__device__ __forceinline__ ull dot8p(const ull h[8], const ull T[8]) {
    ull s0 = f2mul(h[0], T[0]);
    ull s1 = f2mul(h[1], T[1]);
    s0 = f2fma(h[2], T[2], s0); s1 = f2fma(h[3], T[3], s1);
    s0 = f2fma(h[4], T[4], s0); s1 = f2fma(h[5], T[5], s1);
    s0 = f2fma(h[6], T[6], s0); s1 = f2fma(h[7], T[7], s1);
    return f2add(s0, s1);
}
__device__ __forceinline__ float coldot(const ull h[8], const ulonglong2* __restrict__ c) {
    ulonglong2 c0 = c[0], c1 = c[1], c2 = c[2], c3 = c[3];
    ull s0 = f2mul(h[0], c0.x);
    ull s1 = f2mul(h[1], c0.y);
    s0 = f2fma(h[2], c1.x, s0); s1 = f2fma(h[3], c1.y, s1);
    s0 = f2fma(h[4], c2.x, s0); s1 = f2fma(h[5], c2.y, s1);
    s0 = f2fma(h[6], c3.x, s0); s1 = f2fma(h[7], c3.y, s1);
    float2 r = upk(f2add(s0, s1));
    return r.x + r.y;
}

// lerp 16-wide table row -> 8 packed regs
__device__ __forceinline__ void table_lerp(const float* __restrict__ tab, float d, ull h2[8]) {
    float uu = d * ((float)(TBL - 1) * 0.125f);
    int i0 = (int)uu;
    if (i0 < 0) i0 = 0;
    if (i0 > TBL - 2) i0 = TBL - 2;
    float f = uu - (float)i0;
    const float4* t0 = reinterpret_cast<const float4*>(tab + i0 * 16);
    #pragma unroll
    for (int k = 0; k < 4; ++k) {
        float4 A = t0[k], B = t0[k + 4];
        float h0 = fmaf(f, B.x - A.x, A.x);
        float h1 = fmaf(f, B.y - A.y, A.y);
        float h2v = fmaf(f, B.z - A.z, A.z);
        float h3 = fmaf(f, B.w - A.w, A.w);
        h2[2 * k] = pk(h0, h1);
        h2[2 * k + 1] = pk(h2v, h3);
    }
}

// -------- setup: weight transpose + radial MLP tables
__global__ void setup_kernel(const float* __restrict__ Wk2, const float* __restrict__ Wv2,
                             const float* __restrict__ Wk1, const float* __restrict__ Wv1) {
    int idx = blockIdx.x * 256 + threadIdx.x;
    if (idx < 9216) {
        g_WkT[idx] = Wk2[(idx & 15) * 576 + (idx >> 4)];
    } else if (idx < 18432) {
        int t = idx - 9216;
        g_WvT[t] = Wv2[(t & 15) * 576 + (t >> 4)];
    } else if (idx < 18432 + TBL) {
        int i = idx - 18432;
        float d = (float)i * (8.0f / (float)(TBL - 1));
        float emb[16];
        #pragma unroll
        for (int b = 0; b < 16; ++b) {
            float cb = 0.47058824f * (float)(b + 1);
            float diff = (d - cb) * 2.125f;
            float q = 1.0f - diff * diff;
            emb[b] = (q > 0.f) ? 33.7342930f * expf(-2.0f / q) : 0.f;
        }
        #pragma unroll
        for (int c = 0; c < 16; ++c) {
            float sk = 0.f, sv = 0.f;
            #pragma unroll
            for (int b = 0; b < 16; ++b) {
                sk = fmaf(emb[b], Wk1[b * 16 + c], sk);
                sv = fmaf(emb[b], Wv1[b * 16 + c], sv);
            }
            sk *= 0.25f; sv *= 0.25f;
            g_tk[i * 16 + c] = sk / (1.f + expf(-sk));
            g_tv[i * 16 + c] = sv / (1.f + expf(-sv));
        }
    }
}

// -------- per-node p0/p1 = x(WqWd) with norms folded; zero z and out
__global__ __launch_bounds__(128) void node_prep(
    const float* __restrict__ x,
    const float* __restrict__ Wq0, const float* __restrict__ Wq1,
    const float* __restrict__ Wd0, const float* __restrict__ Wd1,
    float* __restrict__ out, int n) {
    __shared__ float C0[256];
    __shared__ float C1[64];
    int t = threadIdx.x;
    for (int idx = t; idx < 256; idx += blockDim.x) {
        int u = idx >> 4, v = idx & 15;
        float s = 0.f;
        #pragma unroll
        for (int w = 0; w < 16; ++w) s = fmaf(Wq0[u * 16 + w], Wd0[w * 16 + v], s);
        C0[idx] = s * 0.25f;
    }
    if (t < 64) {
        int u = t >> 3, v = t & 7;
        float s = 0.f;
        #pragma unroll
        for (int w = 0; w < 8; ++w) s = fmaf(Wq1[u * 8 + w], Wd1[w * 8 + v], s);
        C1[t] = s * 0.2041241452f;  // 1/(sqrt(8)*sqrt(3))
    }
    __syncthreads();
    int i = blockIdx.x * blockDim.x + t;
    if (i >= n) return;

    float x0[16];
    #pragma unroll
    for (int u = 0; u < 16; ++u) x0[u] = x[i * 40 + u];
    #pragma unroll
    for (int v = 0; v < 16; ++v) {
        float s = 0.f;
        #pragma unroll
        for (int u = 0; u < 16; ++u) s = fmaf(x0[u], C0[u * 16 + v], s);
        g_p0[i * 16 + v] = s;
    }
    float x1[24];
    #pragma unroll
    for (int k = 0; k < 24; ++k) x1[k] = x[i * 40 + 16 + k];
    #pragma unroll
    for (int v = 0; v < 8; ++v) {
        #pragma unroll
        for (int c = 0; c < 3; ++c) {
            float s = 0.f;
            #pragma unroll
            for (int u = 0; u < 8; ++u) s = fmaf(x1[u * 3 + c], C1[u * 8 + v], s);
            g_p1[i * 24 + v * 3 + c] = s;
        }
    }
    g_z[i] = 0.f;
    float4 z4 = make_float4(0.f, 0.f, 0.f, 0.f);
    float4* o4 = reinterpret_cast<float4*>(out + i * 40);
    #pragma unroll
    for (int m = 0; m < 10; ++m) o4[m] = z4;
}

// -------- score kernel: one thread per edge, Wk in smem
__global__ __launch_bounds__(128) void edge_score(
    const float* __restrict__ x, const int* __restrict__ ei,
    const float* __restrict__ ea, const float* __restrict__ amf, int E) {
    __shared__ __align__(16) float Wk[9216];
    {
        float4* s4 = reinterpret_cast<float4*>(Wk);
        const float4* g4 = reinterpret_cast<const float4*>(g_WkT);
        for (int i = threadIdx.x; i < 2304; i += 128) s4[i] = g4[i];
    }
    __syncthreads();
    int e = blockIdx.x * 128 + threadIdx.x;
    if (e >= E) return;

    int src = ei[e], dst = ei[E + e];
    const float4 sh = reinterpret_cast<const float4*>(ea)[e];
    const float sh0 = sh.x, s1x = sh.y, s1y = sh.z, s1z = sh.w;
    const float d = amf[e];
    const ulonglong2* WK = reinterpret_cast<const ulonglong2*>(Wk);

    float x0r[16];
    {
        const float4* xp4 = reinterpret_cast<const float4*>(x + src * 40);
        float4 t0 = xp4[0], t1 = xp4[1], t2 = xp4[2], t3 = xp4[3];
        x0r[0] = t0.x; x0r[1] = t0.y; x0r[2] = t0.z; x0r[3] = t0.w;
        x0r[4] = t1.x; x0r[5] = t1.y; x0r[6] = t1.z; x0r[7] = t1.w;
        x0r[8] = t2.x; x0r[9] = t2.y; x0r[10] = t2.z; x0r[11] = t2.w;
        x0r[12] = t3.x; x0r[13] = t3.y; x0r[14] = t3.z; x0r[15] = t3.w;
    }
    float p0[16];
    {
        const float4* pp = reinterpret_cast<const float4*>(g_p0 + dst * 16);
        float4 t0 = pp[0], t1 = pp[1], t2 = pp[2], t3 = pp[3];
        p0[0] = t0.x; p0[1] = t0.y; p0[2] = t0.z; p0[3] = t0.w;
        p0[4] = t1.x; p0[5] = t1.y; p0[6] = t1.z; p0[7] = t1.w;
        p0[8] = t2.x; p0[9] = t2.y; p0[10] = t2.z; p0[11] = t2.w;
        p0[12] = t3.x; p0[13] = t3.y; p0[14] = t3.z; p0[15] = t3.w;
    }

    ull m[8];
    // block1: j=u*16+w, g = (x0[u]*sh0) * p0[w]
    {
        float au = x0r[0] * sh0;
        colmul8(m, WK, pk2(au * p0[0]));
        #pragma unroll
        for (int w = 1; w < 16; ++w) colfma8(m, WK + w * 4, pk2(au * p0[w]));
    }
    #pragma unroll 1
    for (int u = 1; u < 16; ++u) {
        float au = x0r[u] * sh0;
        #pragma unroll
        for (int w = 0; w < 16; ++w) colfma8(m, WK + (u * 16 + w) * 4, pk2(au * p0[w]));
    }
    // x1 + dd
    float x1r[24];
    {
        const float4* xp4 = reinterpret_cast<const float4*>(x + src * 40);
        #pragma unroll
        for (int k = 0; k < 6; ++k) {
            float4 t = xp4[4 + k];
            x1r[4 * k] = t.x; x1r[4 * k + 1] = t.y; x1r[4 * k + 2] = t.z; x1r[4 * k + 3] = t.w;
        }
    }
    float dd[8];
    #pragma unroll
    for (int u = 0; u < 8; ++u)
        dd[u] = (x1r[3 * u] * s1x + x1r[3 * u + 1] * s1y + x1r[3 * u + 2] * s1z) * 0.57735027f;
    // block4: j=448+u*16+w, g = dd[u]*p0[w]
    #pragma unroll 1
    for (int u = 0; u < 8; ++u) {
        float du = dd[u];
        #pragma unroll
        for (int w = 0; w < 16; ++w) colfma8(m, WK + (448 + u * 16 + w) * 4, pk2(du * p0[w]));
    }
    // p1, r
    float p1[24];
    {
        const float4* pp = reinterpret_cast<const float4*>(g_p1 + dst * 24);
        #pragma unroll
        for (int k = 0; k < 6; ++k) {
            float4 t = pp[k];
            p1[4 * k] = t.x; p1[4 * k + 1] = t.y; p1[4 * k + 2] = t.z; p1[4 * k + 3] = t.w;
        }
    }
    float r[8];
    #pragma unroll
    for (int w = 0; w < 8; ++w)
        r[w] = p1[3 * w] * s1x + p1[3 * w + 1] * s1y + p1[3 * w + 2] * s1z;
    // block2: j=256+u*8+w, g = x0[u]*r[w]
    #pragma unroll 1
    for (int u = 0; u < 16; ++u) {
        float xu = x0r[u];
        #pragma unroll
        for (int w = 0; w < 8; ++w) colfma8(m, WK + (256 + u * 8 + w) * 4, pk2(xu * r[w]));
    }
    // block3: j=384+u*8+w, g = sh0 * (x1[u,:].p1[w,:]); fold sh0 into x1
    #pragma unroll
    for (int k = 0; k < 24; ++k) x1r[k] *= sh0;
    #pragma unroll 1
    for (int u = 0; u < 8; ++u) {
        float a = x1r[3 * u], b = x1r[3 * u + 1], c = x1r[3 * u + 2];
        #pragma unroll
        for (int w = 0; w < 8; ++w) {
            float g = a * p1[3 * w] + b * p1[3 * w + 1] + c * p1[3 * w + 2];
            colfma8(m, WK + (384 + u * 8 + w) * 4, pk2(g));
        }
    }
    // hk (table lerp) only needed now
    ull hk2[8];
    table_lerp(g_tk, d, hk2);
    float2 sc2 = upk(dot8p(hk2, m));
    float score = (sc2.x + sc2.y) * 0.0028527222f;  // 1/(4*sqrt(24)*sqrt(320))
    float tc = 10.0f * (1.0f - d * 0.125f);
    float cut = (tc > 0.f) ? __expf(-__frcp_rn(tc)) : 0.f;
    float ev = cut * __expf(score);
    g_expv[e] = ev;
    atomicAdd(&g_z[dst], ev);
}

// -------- value kernel: one thread per edge, Wv in smem
__global__ __launch_bounds__(128) void edge_value(
    const float* __restrict__ x, const int* __restrict__ ei,
    const float* __restrict__ ea, const float* __restrict__ amf,
    float* __restrict__ out, int E) {
    __shared__ __align__(16) float Wv[9216];
    {
        float4* s4 = reinterpret_cast<float4*>(Wv);
        const float4* g4 = reinterpret_cast<const float4*>(g_WvT);
        for (int i = threadIdx.x; i < 2304; i += 128) s4[i] = g4[i];
    }
    __syncthreads();
    int e = blockIdx.x * 128 + threadIdx.x;
    if (e >= E) return;

    int src = ei[e], dst = ei[E + e];
    const float4 sh = reinterpret_cast<const float4*>(ea)[e];
    const float sh0 = sh.x, s1x = sh.y, s1y = sh.z, s1z = sh.w;
    const float d = amf[e];
    const ulonglong2* WV = reinterpret_cast<const ulonglong2*>(Wv);

    float fs = sqrtf(g_expv[e]) * 0.0510310363f;  // sqrt(ev)/(4*sqrt(24))

    ull hv2[8];
    table_lerp(g_tv, d, hv2);

    float x0r[16];
    {
        const float4* xp4 = reinterpret_cast<const float4*>(x + src * 40);
        float4 t0 = xp4[0], t1 = xp4[1], t2 = xp4[2], t3 = xp4[3];
        x0r[0] = t0.x; x0r[1] = t0.y; x0r[2] = t0.z; x0r[3] = t0.w;
        x0r[4] = t1.x; x0r[5] = t1.y; x0r[6] = t1.z; x0r[7] = t1.w;
        x0r[8] = t2.x; x0r[9] = t2.y; x0r[10] = t2.z; x0r[11] = t2.w;
        x0r[12] = t3.x; x0r[13] = t3.y; x0r[14] = t3.z; x0r[15] = t3.w;
    }
    float x1s[24], dd[8];
    {
        const float4* xp4 = reinterpret_cast<const float4*>(x + src * 40);
        float x1r[24];
        #pragma unroll
        for (int k = 0; k < 6; ++k) {
            float4 t = xp4[4 + k];
            x1r[4 * k] = t.x; x1r[4 * k + 1] = t.y; x1r[4 * k + 2] = t.z; x1r[4 * k + 3] = t.w;
        }
        #pragma unroll
        for (int u = 0; u < 8; ++u) {
            float ra = x1r[3 * u], rb = x1r[3 * u + 1], rc = x1r[3 * u + 2];
            dd[u] = (ra * s1x + rb * s1y + rc * s1z) * 0.57735027f;
            x1s[3 * u] = ra * sh0; x1s[3 * u + 1] = rb * sh0; x1s[3 * u + 2] = rc * sh0;
        }
    }
    float* ob = out + dst * 40;

    // o1[w,:] = (hv . sum_u x0[u] W2col(u,w)) * sh1 + sum_u (hv . W3col(u,w)) * x1s[u,:]
    #pragma unroll 1
    for (int w = 0; w < 8; ++w) {
        ull U[8];
        colmul8(U, WV + (256 + w) * 4, pk2(x0r[0]));
        #pragma unroll
        for (int u = 1; u < 16; ++u) colfma8(U, WV + (256 + u * 8 + w) * 4, pk2(x0r[u]));
        float2 t2 = upk(dot8p(hv2, U));
        float Aw = t2.x + t2.y;
        float vx = Aw * s1x, vy = Aw * s1y, vz = Aw * s1z;
        #pragma unroll
        for (int u = 0; u < 8; ++u) {
            float s = coldot(hv2, WV + (384 + u * 8 + w) * 4);
            vx = fmaf(s, x1s[3 * u], vx);
            vy = fmaf(s, x1s[3 * u + 1], vy);
            vz = fmaf(s, x1s[3 * u + 2], vz);
        }
        atomicAdd(ob + 16 + 3 * w, vx * fs);
        atomicAdd(ob + 17 + 3 * w, vy * fs);
        atomicAdd(ob + 18 + 3 * w, vz * fs);
    }
    // a0 = x0 * sh0 (in place); o0[w] = hv . (sum_u a0[u] W1col + sum_u dd[u] W4col)
    #pragma unroll
    for (int u = 0; u < 16; ++u) x0r[u] *= sh0;
    #pragma unroll 1
    for (int w = 0; w < 16; ++w) {
        ull U[8];
        colmul8(U, WV + w * 4, pk2(x0r[0]));
        #pragma unroll
        for (int u = 1; u < 16; ++u) colfma8(U, WV + (u * 16 + w) * 4, pk2(x0r[u]));
        #pragma unroll
        for (int u = 0; u < 8; ++u) colfma8(U, WV + (448 + u * 16 + w) * 4, pk2(dd[u]));
        float2 s2 = upk(dot8p(hv2, U));
        atomicAdd(ob + w, (s2.x + s2.y) * fs);
    }
}

// -------- epilogue: out[i] *= rsqrt(z[i])
__global__ void normalize(float* __restrict__ out, int n) {
    int i = blockIdx.x * 128 + threadIdx.x;
    if (i >= n) return;
    float zz = g_z[i];
    if (zz <= 0.f) zz = 1.f;
    float s = rsqrtf(zz);
    float4* o4 = reinterpret_cast<float4*>(out + i * 40);
    #pragma unroll
    for (int m = 0; m < 10; ++m) {
        float4 v = o4[m];
        v.x *= s; v.y *= s; v.z *= s; v.w *= s;
        o4[m] = v;
    }
}

extern "C" void kernel_launch(void* const* d_in, const int* in_sizes, int n_in,
                              void* d_out, int out_size) {
    const float* x   = (const float*)d_in[0];
    const int*   ei  = (const int*)d_in[1];
    const float* ea  = (const float*)d_in[2];
    const float* amf = (const float*)d_in[5];
    const float* Wq0 = (const float*)d_in[6];
    const float* Wq1 = (const float*)d_in[7];
    const float* Wk1 = (const float*)d_in[8];
    const float* Wk2 = (const float*)d_in[9];
    const float* Wv1 = (const float*)d_in[10];
    const float* Wv2 = (const float*)d_in[11];
    const float* Wd0 = (const float*)d_in[12];
    const float* Wd1 = (const float*)d_in[13];
    float* out = (float*)d_out;

    int n = in_sizes[0] / 40;
    int E = in_sizes[2] / 4;

    setup_kernel<<<(18432 + TBL + 255) / 256, 256>>>(Wk2, Wv2, Wk1, Wv1);
    node_prep<<<(n + 127) / 128, 128>>>(x, Wq0, Wq1, Wd0, Wd1, out, n);
    int grid = (E + 127) / 128;
    edge_score<<<grid, 128>>>(x, ei, ea, amf, E);
    edge_value<<<grid, 128>>>(x, ei, ea, amf, out, E);
    normalize<<<(n + 127) / 128, 128>>>(out, n);
}

// round 5
// speedup vs baseline: 1.5688x; 1.1694x over previous
#include <cuda_runtime.h>
#include <math.h>

#define NMAX 10000
#define EMAX 160000
#define TBL 16384
typedef unsigned long long ull;

// device scratch (no runtime allocation)
__device__ float g_p0[NMAX * 16];
__device__ float g_p1[NMAX * 24];
__device__ float g_z[NMAX];
__device__ float g_expv[EMAX];
__device__ float g_WkT[9216];      // [j*16+c]
__device__ float g_WvT[9216];
__device__ float g_tk[TBL * 16];   // hk(d) table
__device__ float g_tv[TBL * 16];   // hv(d) table

// ---------- packed f32x2 primitives ----------
__device__ __forceinline__ ull pk2(float a) {
    ull r; asm("mov.b64 %0, {%1,%1};" : "=l"(r) : "f"(a)); return r;
}
__device__ __forceinline__ ull pk(float a, float b) {
    ull r; asm("mov.b64 %0, {%1,%2};" : "=l"(r) : "f"(a), "f"(b)); return r;
}
__device__ __forceinline__ float2 upk(ull a) {
    float2 f; asm("mov.b64 {%0,%1}, %2;" : "=f"(f.x), "=f"(f.y) : "l"(a)); return f;
}
__device__ __forceinline__ ull f2fma(ull a, ull b, ull c) {
    ull d; asm("fma.rn.f32x2 %0, %1, %2, %3;" : "=l"(d) : "l"(a), "l"(b), "l"(c)); return d;
}
__device__ __forceinline__ ull f2mul(ull a, ull b) {
    ull d; asm("mul.rn.f32x2 %0, %1, %2;" : "=l"(d) : "l"(a), "l"(b)); return d;
}
__device__ __forceinline__ ull f2add(ull a, ull b) {
    ull d; asm("add.rn.f32x2 %0, %1, %2;" : "=l"(d) : "l"(a), "l"(b)); return d;
}

// load a 16-float column once, FMA into BOTH edges' 8 packed accumulators
__device__ __forceinline__ void colfma8_2(ull A[8], ull B[8],
                                          const ulonglong2* __restrict__ c,
                                          ull fa, ull fb) {
    ulonglong2 c0 = c[0], c1 = c[1], c2 = c[2], c3 = c[3];
    A[0] = f2fma(fa, c0.x, A[0]); B[0] = f2fma(fb, c0.x, B[0]);
    A[1] = f2fma(fa, c0.y, A[1]); B[1] = f2fma(fb, c0.y, B[1]);
    A[2] = f2fma(fa, c1.x, A[2]); B[2] = f2fma(fb, c1.x, B[2]);
    A[3] = f2fma(fa, c1.y, A[3]); B[3] = f2fma(fb, c1.y, B[3]);
    A[4] = f2fma(fa, c2.x, A[4]); B[4] = f2fma(fb, c2.x, B[4]);
    A[5] = f2fma(fa, c2.y, A[5]); B[5] = f2fma(fb, c2.y, B[5]);
    A[6] = f2fma(fa, c3.x, A[6]); B[6] = f2fma(fb, c3.x, B[6]);
    A[7] = f2fma(fa, c3.y, A[7]); B[7] = f2fma(fb, c3.y, B[7]);
}
__device__ __forceinline__ ull dot8p(const ull h[8], const ull T[8]) {
    ull s0 = f2mul(h[0], T[0]);
    ull s1 = f2mul(h[1], T[1]);
    s0 = f2fma(h[2], T[2], s0); s1 = f2fma(h[3], T[3], s1);
    s0 = f2fma(h[4], T[4], s0); s1 = f2fma(h[5], T[5], s1);
    s0 = f2fma(h[6], T[6], s0); s1 = f2fma(h[7], T[7], s1);
    return f2add(s0, s1);
}
// two coldots sharing one column load
__device__ __forceinline__ void coldot2(const ull hA[8], const ull hB[8],
                                        const ulonglong2* __restrict__ c,
                                        float& oA, float& oB) {
    ulonglong2 c0 = c[0], c1 = c[1], c2 = c[2], c3 = c[3];
    ull a0 = f2mul(hA[0], c0.x), a1 = f2mul(hA[1], c0.y);
    ull b0 = f2mul(hB[0], c0.x), b1 = f2mul(hB[1], c0.y);
    a0 = f2fma(hA[2], c1.x, a0); a1 = f2fma(hA[3], c1.y, a1);
    b0 = f2fma(hB[2], c1.x, b0); b1 = f2fma(hB[3], c1.y, b1);
    a0 = f2fma(hA[4], c2.x, a0); a1 = f2fma(hA[5], c2.y, a1);
    b0 = f2fma(hB[4], c2.x, b0); b1 = f2fma(hB[5], c2.y, b1);
    a0 = f2fma(hA[6], c3.x, a0); a1 = f2fma(hA[7], c3.y, a1);
    b0 = f2fma(hB[6], c3.x, b0); b1 = f2fma(hB[7], c3.y, b1);
    float2 ra = upk(f2add(a0, a1)); oA = ra.x + ra.y;
    float2 rb = upk(f2add(b0, b1)); oB = rb.x + rb.y;
}

__device__ __forceinline__ void ld16(float o[16], const float* __restrict__ p) {
    const float4* p4 = reinterpret_cast<const float4*>(p);
    float4 t0 = p4[0], t1 = p4[1], t2 = p4[2], t3 = p4[3];
    o[0] = t0.x; o[1] = t0.y; o[2] = t0.z; o[3] = t0.w;
    o[4] = t1.x; o[5] = t1.y; o[6] = t1.z; o[7] = t1.w;
    o[8] = t2.x; o[9] = t2.y; o[10] = t2.z; o[11] = t2.w;
    o[12] = t3.x; o[13] = t3.y; o[14] = t3.z; o[15] = t3.w;
}
__device__ __forceinline__ void ld24(float o[24], const float* __restrict__ p) {
    const float4* p4 = reinterpret_cast<const float4*>(p);
    #pragma unroll
    for (int k = 0; k < 6; ++k) {
        float4 t = p4[k];
        o[4 * k] = t.x; o[4 * k + 1] = t.y; o[4 * k + 2] = t.z; o[4 * k + 3] = t.w;
    }
}

// lerp 16-wide table row -> 8 packed regs
__device__ __forceinline__ void table_lerp(const float* __restrict__ tab, float d, ull h2[8]) {
    float uu = d * ((float)(TBL - 1) * 0.125f);
    int i0 = (int)uu;
    if (i0 < 0) i0 = 0;
    if (i0 > TBL - 2) i0 = TBL - 2;
    float f = uu - (float)i0;
    const float4* t0 = reinterpret_cast<const float4*>(tab + i0 * 16);
    #pragma unroll
    for (int k = 0; k < 4; ++k) {
        float4 A = t0[k], B = t0[k + 4];
        float h0 = fmaf(f, B.x - A.x, A.x);
        float h1 = fmaf(f, B.y - A.y, A.y);
        float h2v = fmaf(f, B.z - A.z, A.z);
        float h3 = fmaf(f, B.w - A.w, A.w);
        h2[2 * k] = pk(h0, h1);
        h2[2 * k + 1] = pk(h2v, h3);
    }
}

// -------- setup: weight transpose + radial MLP tables
__global__ void setup_kernel(const float* __restrict__ Wk2, const float* __restrict__ Wv2,
                             const float* __restrict__ Wk1, const float* __restrict__ Wv1) {
    int idx = blockIdx.x * 256 + threadIdx.x;
    if (idx < 9216) {
        g_WkT[idx] = Wk2[(idx & 15) * 576 + (idx >> 4)];
    } else if (idx < 18432) {
        int t = idx - 9216;
        g_WvT[t] = Wv2[(t & 15) * 576 + (t >> 4)];
    } else if (idx < 18432 + TBL) {
        int i = idx - 18432;
        float d = (float)i * (8.0f / (float)(TBL - 1));
        float emb[16];
        #pragma unroll
        for (int b = 0; b < 16; ++b) {
            float cb = 0.47058824f * (float)(b + 1);
            float diff = (d - cb) * 2.125f;
            float q = 1.0f - diff * diff;
            emb[b] = (q > 0.f) ? 33.7342930f * expf(-2.0f / q) : 0.f;
        }
        #pragma unroll
        for (int c = 0; c < 16; ++c) {
            float sk = 0.f, sv = 0.f;
            #pragma unroll
            for (int b = 0; b < 16; ++b) {
                sk = fmaf(emb[b], Wk1[b * 16 + c], sk);
                sv = fmaf(emb[b], Wv1[b * 16 + c], sv);
            }
            sk *= 0.25f; sv *= 0.25f;
            g_tk[i * 16 + c] = sk / (1.f + expf(-sk));
            g_tv[i * 16 + c] = sv / (1.f + expf(-sv));
        }
    }
}

// -------- per-node p0/p1 = x(WqWd) with norms folded; zero z and out
__global__ __launch_bounds__(128) void node_prep(
    const float* __restrict__ x,
    const float* __restrict__ Wq0, const float* __restrict__ Wq1,
    const float* __restrict__ Wd0, const float* __restrict__ Wd1,
    float* __restrict__ out, int n) {
    __shared__ float C0[256];
    __shared__ float C1[64];
    int t = threadIdx.x;
    for (int idx = t; idx < 256; idx += blockDim.x) {
        int u = idx >> 4, v = idx & 15;
        float s = 0.f;
        #pragma unroll
        for (int w = 0; w < 16; ++w) s = fmaf(Wq0[u * 16 + w], Wd0[w * 16 + v], s);
        C0[idx] = s * 0.25f;
    }
    if (t < 64) {
        int u = t >> 3, v = t & 7;
        float s = 0.f;
        #pragma unroll
        for (int w = 0; w < 8; ++w) s = fmaf(Wq1[u * 8 + w], Wd1[w * 8 + v], s);
        C1[t] = s * 0.2041241452f;  // 1/(sqrt(8)*sqrt(3))
    }
    __syncthreads();
    int i = blockIdx.x * blockDim.x + t;
    if (i >= n) return;

    float x0[16];
    #pragma unroll
    for (int u = 0; u < 16; ++u) x0[u] = x[i * 40 + u];
    #pragma unroll
    for (int v = 0; v < 16; ++v) {
        float s = 0.f;
        #pragma unroll
        for (int u = 0; u < 16; ++u) s = fmaf(x0[u], C0[u * 16 + v], s);
        g_p0[i * 16 + v] = s;
    }
    float x1[24];
    #pragma unroll
    for (int k = 0; k < 24; ++k) x1[k] = x[i * 40 + 16 + k];
    #pragma unroll
    for (int v = 0; v < 8; ++v) {
        #pragma unroll
        for (int c = 0; c < 3; ++c) {
            float s = 0.f;
            #pragma unroll
            for (int u = 0; u < 8; ++u) s = fmaf(x1[u * 3 + c], C1[u * 8 + v], s);
            g_p1[i * 24 + v * 3 + c] = s;
        }
    }
    g_z[i] = 0.f;
    float4 z4 = make_float4(0.f, 0.f, 0.f, 0.f);
    float4* o4 = reinterpret_cast<float4*>(out + i * 40);
    #pragma unroll
    for (int m = 0; m < 10; ++m) o4[m] = z4;
}

// -------- score kernel: TWO edges per thread, Wk column read once for both
__global__ __launch_bounds__(128) void edge_score(
    const float* __restrict__ x, const int* __restrict__ ei,
    const float* __restrict__ ea, const float* __restrict__ amf, int E) {
    __shared__ __align__(16) float Wk[9216];
    {
        float4* s4 = reinterpret_cast<float4*>(Wk);
        const float4* g4 = reinterpret_cast<const float4*>(g_WkT);
        for (int i = threadIdx.x; i < 2304; i += 128) s4[i] = g4[i];
    }
    __syncthreads();
    const ulonglong2* WK = reinterpret_cast<const ulonglong2*>(Wk);

    int e0 = blockIdx.x * 256 + threadIdx.x;
    int e1 = e0 + 128;
    bool v0 = e0 < E, v1 = e1 < E;
    int ia = v0 ? e0 : 0, ib = v1 ? e1 : 0;
    int srcA = ei[ia], dstA = ei[E + ia];
    int srcB = ei[ib], dstB = ei[E + ib];
    const float4 shA = reinterpret_cast<const float4*>(ea)[ia];
    const float4 shB = reinterpret_cast<const float4*>(ea)[ib];
    float dA = amf[ia], dB = amf[ib];

    float x0A[16], x0B[16], p0A[16], p0B[16];
    ld16(x0A, x + srcA * 40); ld16(x0B, x + srcB * 40);
    ld16(p0A, g_p0 + dstA * 16); ld16(p0B, g_p0 + dstB * 16);

    ull mA[8], mB[8];
    #pragma unroll
    for (int i = 0; i < 8; ++i) { mA[i] = pk2(0.f); mB[i] = pk2(0.f); }

    // block1: j=u*16+w, g = (x0[u]*sh0)*p0[w]
    #pragma unroll 1
    for (int u = 0; u < 16; ++u) {
        float aA = x0A[u] * shA.x, aB = x0B[u] * shB.x;
        #pragma unroll
        for (int w = 0; w < 16; ++w)
            colfma8_2(mA, mB, WK + (u * 16 + w) * 4, pk2(aA * p0A[w]), pk2(aB * p0B[w]));
    }
    // r from p1 (streamed, discarded)
    float rA[8], rB[8];
    {
        float tA[24], tB[24];
        ld24(tA, g_p1 + dstA * 24); ld24(tB, g_p1 + dstB * 24);
        #pragma unroll
        for (int w = 0; w < 8; ++w) {
            rA[w] = tA[3 * w] * shA.y + tA[3 * w + 1] * shA.z + tA[3 * w + 2] * shA.w;
            rB[w] = tB[3 * w] * shB.y + tB[3 * w + 1] * shB.z + tB[3 * w + 2] * shB.w;
        }
    }
    // block2: j=256+u*8+w, g = x0[u]*r[w]
    #pragma unroll 1
    for (int u = 0; u < 16; ++u) {
        float xA = x0A[u], xB = x0B[u];
        #pragma unroll
        for (int w = 0; w < 8; ++w)
            colfma8_2(mA, mB, WK + (256 + u * 8 + w) * 4, pk2(xA * rA[w]), pk2(xB * rB[w]));
    }
    // dd (x1 streamed, discarded)
    float ddA[8], ddB[8];
    {
        float tA[24], tB[24];
        ld24(tA, x + srcA * 40 + 16); ld24(tB, x + srcB * 40 + 16);
        #pragma unroll
        for (int u = 0; u < 8; ++u) {
            ddA[u] = (tA[3 * u] * shA.y + tA[3 * u + 1] * shA.z + tA[3 * u + 2] * shA.w) * 0.57735027f;
            ddB[u] = (tB[3 * u] * shB.y + tB[3 * u + 1] * shB.z + tB[3 * u + 2] * shB.w) * 0.57735027f;
        }
    }
    // block4: j=448+u*16+w, g = dd[u]*p0[w]
    #pragma unroll 1
    for (int u = 0; u < 8; ++u) {
        float aA = ddA[u], aB = ddB[u];
        #pragma unroll
        for (int w = 0; w < 16; ++w)
            colfma8_2(mA, mB, WK + (448 + u * 16 + w) * 4, pk2(aA * p0A[w]), pk2(aB * p0B[w]));
    }
    // block3: j=384+u*8+w, g = (x1*sh0)·p1[w]; x1 resident, p1 streamed per w
    float x1A[24], x1B[24];
    ld24(x1A, x + srcA * 40 + 16); ld24(x1B, x + srcB * 40 + 16);
    #pragma unroll
    for (int k = 0; k < 24; ++k) { x1A[k] *= shA.x; x1B[k] *= shB.x; }
    {
        const float* pA = g_p1 + dstA * 24;
        const float* pB = g_p1 + dstB * 24;
        #pragma unroll 1
        for (int w = 0; w < 8; ++w) {
            float qA0 = pA[3 * w], qA1 = pA[3 * w + 1], qA2 = pA[3 * w + 2];
            float qB0 = pB[3 * w], qB1 = pB[3 * w + 1], qB2 = pB[3 * w + 2];
            #pragma unroll
            for (int u = 0; u < 8; ++u) {
                float gA = x1A[3 * u] * qA0 + x1A[3 * u + 1] * qA1 + x1A[3 * u + 2] * qA2;
                float gB = x1B[3 * u] * qB0 + x1B[3 * u + 1] * qB1 + x1B[3 * u + 2] * qB2;
                colfma8_2(mA, mB, WK + (384 + u * 8 + w) * 4, pk2(gA), pk2(gB));
            }
        }
    }
    // finalize (reuse one hk buffer for both edges)
    ull hk[8];
    table_lerp(g_tk, dA, hk);
    float2 sA2 = upk(dot8p(hk, mA));
    table_lerp(g_tk, dB, hk);
    float2 sB2 = upk(dot8p(hk, mB));
    float scoreA = (sA2.x + sA2.y) * 0.0028527222f;
    float scoreB = (sB2.x + sB2.y) * 0.0028527222f;
    float tcA = 10.0f * (1.0f - dA * 0.125f);
    float tcB = 10.0f * (1.0f - dB * 0.125f);
    float cutA = (tcA > 0.f) ? __expf(-__frcp_rn(tcA)) : 0.f;
    float cutB = (tcB > 0.f) ? __expf(-__frcp_rn(tcB)) : 0.f;
    float evA = cutA * __expf(scoreA);
    float evB = cutB * __expf(scoreB);
    if (v0) { g_expv[e0] = evA; atomicAdd(&g_z[dstA], evA); }
    if (v1) { g_expv[e1] = evB; atomicAdd(&g_z[dstB], evB); }
}

// -------- value kernel: TWO edges per thread
__global__ __launch_bounds__(128) void edge_value(
    const float* __restrict__ x, const int* __restrict__ ei,
    const float* __restrict__ ea, const float* __restrict__ amf,
    float* __restrict__ out, int E) {
    __shared__ __align__(16) float Wv[9216];
    {
        float4* s4 = reinterpret_cast<float4*>(Wv);
        const float4* g4 = reinterpret_cast<const float4*>(g_WvT);
        for (int i = threadIdx.x; i < 2304; i += 128) s4[i] = g4[i];
    }
    __syncthreads();
    const ulonglong2* WV = reinterpret_cast<const ulonglong2*>(Wv);

    int e0 = blockIdx.x * 256 + threadIdx.x;
    int e1 = e0 + 128;
    bool v0 = e0 < E, v1 = e1 < E;
    int ia = v0 ? e0 : 0, ib = v1 ? e1 : 0;
    int srcA = ei[ia], dstA = ei[E + ia];
    int srcB = ei[ib], dstB = ei[E + ib];
    const float4 shA = reinterpret_cast<const float4*>(ea)[ia];
    const float4 shB = reinterpret_cast<const float4*>(ea)[ib];
    float dA = amf[ia], dB = amf[ib];

    float fsA = sqrtf(g_expv[ia]) * 0.0510310363f;
    float fsB = sqrtf(g_expv[ib]) * 0.0510310363f;

    ull hvA[8], hvB[8];
    table_lerp(g_tv, dA, hvA);
    table_lerp(g_tv, dB, hvB);

    float x0A[16], x0B[16];
    ld16(x0A, x + srcA * 40); ld16(x0B, x + srcB * 40);

    // A-phase: A[w] = hv . (sum_u x0[u] W2col(u,w)), cols 256+u*8+w
    float AA[8], AB[8];
    #pragma unroll 1
    for (int w = 0; w < 8; ++w) {
        ull UA[8], UB[8];
        #pragma unroll
        for (int i = 0; i < 8; ++i) { UA[i] = pk2(0.f); UB[i] = pk2(0.f); }
        #pragma unroll
        for (int u = 0; u < 16; ++u)
            colfma8_2(UA, UB, WV + (256 + u * 8 + w) * 4, pk2(x0A[u]), pk2(x0B[u]));
        float2 tA = upk(dot8p(hvA, UA)); AA[w] = tA.x + tA.y;
        float2 tB = upk(dot8p(hvB, UB)); AB[w] = tB.x + tB.y;
    }
    // dd (x1 streamed)
    float ddA[8], ddB[8];
    {
        float tA[24], tB[24];
        ld24(tA, x + srcA * 40 + 16); ld24(tB, x + srcB * 40 + 16);
        #pragma unroll
        for (int u = 0; u < 8; ++u) {
            ddA[u] = (tA[3 * u] * shA.y + tA[3 * u + 1] * shA.z + tA[3 * u + 2] * shA.w) * 0.57735027f;
            ddB[u] = (tB[3 * u] * shB.y + tB[3 * u + 1] * shB.z + tB[3 * u + 2] * shB.w) * 0.57735027f;
        }
    }
    float* obA = out + dstA * 40;
    float* obB = out + dstB * 40;

    // o0: scale x0 in place to a0 = x0*sh0; per w: U over block1(16,a0) + block4(8,dd)
    #pragma unroll
    for (int u = 0; u < 16; ++u) { x0A[u] *= shA.x; x0B[u] *= shB.x; }
    #pragma unroll 1
    for (int w = 0; w < 16; ++w) {
        ull UA[8], UB[8];
        #pragma unroll
        for (int i = 0; i < 8; ++i) { UA[i] = pk2(0.f); UB[i] = pk2(0.f); }
        #pragma unroll
        for (int u = 0; u < 16; ++u)
            colfma8_2(UA, UB, WV + (u * 16 + w) * 4, pk2(x0A[u]), pk2(x0B[u]));
        #pragma unroll
        for (int u = 0; u < 8; ++u)
            colfma8_2(UA, UB, WV + (448 + u * 16 + w) * 4, pk2(ddA[u]), pk2(ddB[u]));
        float2 sA = upk(dot8p(hvA, UA));
        float2 sB = upk(dot8p(hvB, UB));
        if (v0) atomicAdd(obA + w, (sA.x + sA.y) * fsA);
        if (v1) atomicAdd(obB + w, (sB.x + sB.y) * fsB);
    }
    // o1: x1s resident; per w: vxyz = A[w]*sh1 + sum_u (hv.W3col)*x1s[u,:]
    float x1A[24], x1B[24];
    ld24(x1A, x + srcA * 40 + 16); ld24(x1B, x + srcB * 40 + 16);
    #pragma unroll
    for (int k = 0; k < 24; ++k) { x1A[k] *= shA.x; x1B[k] *= shB.x; }
    #pragma unroll 1
    for (int w = 0; w < 8; ++w) {
        float vxA = AA[w] * shA.y, vyA = AA[w] * shA.z, vzA = AA[w] * shA.w;
        float vxB = AB[w] * shB.y, vyB = AB[w] * shB.z, vzB = AB[w] * shB.w;
        #pragma unroll
        for (int u = 0; u < 8; ++u) {
            float sA_, sB_;
            coldot2(hvA, hvB, WV + (384 + u * 8 + w) * 4, sA_, sB_);
            vxA = fmaf(sA_, x1A[3 * u], vxA);
            vyA = fmaf(sA_, x1A[3 * u + 1], vyA);
            vzA = fmaf(sA_, x1A[3 * u + 2], vzA);
            vxB = fmaf(sB_, x1B[3 * u], vxB);
            vyB = fmaf(sB_, x1B[3 * u + 1], vyB);
            vzB = fmaf(sB_, x1B[3 * u + 2], vzB);
        }
        if (v0) {
            atomicAdd(obA + 16 + 3 * w, vxA * fsA);
            atomicAdd(obA + 17 + 3 * w, vyA * fsA);
            atomicAdd(obA + 18 + 3 * w, vzA * fsA);
        }
        if (v1) {
            atomicAdd(obB + 16 + 3 * w, vxB * fsB);
            atomicAdd(obB + 17 + 3 * w, vyB * fsB);
            atomicAdd(obB + 18 + 3 * w, vzB * fsB);
        }
    }
}

// -------- epilogue: out[i] *= rsqrt(z[i])
__global__ void normalize(float* __restrict__ out, int n) {
    int i = blockIdx.x * 128 + threadIdx.x;
    if (i >= n) return;
    float zz = g_z[i];
    if (zz <= 0.f) zz = 1.f;
    float s = rsqrtf(zz);
    float4* o4 = reinterpret_cast<float4*>(out + i * 40);
    #pragma unroll
    for (int m = 0; m < 10; ++m) {
        float4 v = o4[m];
        v.x *= s; v.y *= s; v.z *= s; v.w *= s;
        o4[m] = v;
    }
}

extern "C" void kernel_launch(void* const* d_in, const int* in_sizes, int n_in,
                              void* d_out, int out_size) {
    const float* x   = (const float*)d_in[0];
    const int*   ei  = (const int*)d_in[1];
    const float* ea  = (const float*)d_in[2];
    const float* amf = (const float*)d_in[5];
    const float* Wq0 = (const float*)d_in[6];
    const float* Wq1 = (const float*)d_in[7];
    const float* Wk1 = (const float*)d_in[8];
    const float* Wk2 = (const float*)d_in[9];
    const float* Wv1 = (const float*)d_in[10];
    const float* Wv2 = (const float*)d_in[11];
    const float* Wd0 = (const float*)d_in[12];
    const float* Wd1 = (const float*)d_in[13];
    float* out = (float*)d_out;

    int n = in_sizes[0] / 40;
    int E = in_sizes[2] / 4;

    setup_kernel<<<(18432 + TBL + 255) / 256, 256>>>(Wk2, Wv2, Wk1, Wv1);
    node_prep<<<(n + 127) / 128, 128>>>(x, Wq0, Wq1, Wd0, Wd1, out, n);
    int grid = (E + 255) / 256;
    edge_score<<<grid, 128>>>(x, ei, ea, amf, E);
    edge_value<<<grid, 128>>>(x, ei, ea, amf, out, E);
    normalize<<<(n + 127) / 128, 128>>>(out, n);
}